// round 1
// baseline (speedup 1.0000x reference)
#include <cuda_runtime.h>
#include <cuda_bf16.h>

#define N_NODES 100000
#define IN_DIM  256
#define HID     128
#define OUT_DIM 32

// Scratch: h0 = x@W1+b1 [N,128], h1 = relu-pending spmm output [N,128], h2 = h1@W2+b2 [N,32]
__device__ float g_h0[(size_t)N_NODES * HID];
__device__ float g_h1[(size_t)N_NODES * HID];
__device__ float g_h2[(size_t)N_NODES * OUT_DIM];

// ---------------------------------------------------------------------------
// GEMM1: g_h0 = x @ W1 + b1.  M=100000, K=256, N=128.
// Classic 128x128 block, BK=8, 256 threads, 8x8 microtile per thread.
// ---------------------------------------------------------------------------
__global__ __launch_bounds__(256) void gemm1_kernel(const float* __restrict__ X,
                                                    const float* __restrict__ W,
                                                    const float* __restrict__ bias) {
    __shared__ float As[8][128];   // transposed x tile: As[k][m]
    __shared__ float Bs[8][128];   // W tile: Bs[k][n]

    const int block_m = blockIdx.x * 128;
    const int tid = threadIdx.x;
    const int tm = (tid >> 4) << 3;   // 16 row-groups * 8
    const int tn = (tid & 15) << 3;   // 16 col-groups * 8

    float acc[8][8];
#pragma unroll
    for (int i = 0; i < 8; i++)
#pragma unroll
        for (int j = 0; j < 8; j++) acc[i][j] = 0.0f;

    // A-tile load mapping: 128 rows x 8 k -> 256 threads x float4 over k
    const int a_row = tid >> 1;          // 0..127
    const int a_col = (tid & 1) << 2;    // 0 or 4
    // B-tile load mapping: 8 k x 128 n -> 256 threads x float4 over n
    const int b_row = tid >> 5;          // 0..7
    const int b_col = (tid & 31) << 2;   // 0..124

    const bool a_valid = (block_m + a_row) < N_NODES;
    const float* xptr = X + (size_t)(block_m + a_row) * IN_DIM + a_col;

    for (int k0 = 0; k0 < IN_DIM; k0 += 8) {
        float4 av = make_float4(0.f, 0.f, 0.f, 0.f);
        if (a_valid) av = *(const float4*)(xptr + k0);
        As[a_col + 0][a_row] = av.x;
        As[a_col + 1][a_row] = av.y;
        As[a_col + 2][a_row] = av.z;
        As[a_col + 3][a_row] = av.w;

        *(float4*)&Bs[b_row][b_col] =
            *(const float4*)(W + (size_t)(k0 + b_row) * HID + b_col);
        __syncthreads();

#pragma unroll
        for (int k = 0; k < 8; k++) {
            float ar[8], br[8];
#pragma unroll
            for (int i = 0; i < 8; i++) ar[i] = As[k][tm + i];
#pragma unroll
            for (int j = 0; j < 8; j++) br[j] = Bs[k][tn + j];
#pragma unroll
            for (int i = 0; i < 8; i++)
#pragma unroll
                for (int j = 0; j < 8; j++) acc[i][j] += ar[i] * br[j];
        }
        __syncthreads();
    }

    float bv[8];
#pragma unroll
    for (int j = 0; j < 8; j++) bv[j] = bias[tn + j];

#pragma unroll
    for (int i = 0; i < 8; i++) {
        int m = block_m + tm + i;
        if (m < N_NODES) {
            float* orow = g_h0 + (size_t)m * HID + tn;
            float4 v0 = make_float4(acc[i][0] + bv[0], acc[i][1] + bv[1],
                                    acc[i][2] + bv[2], acc[i][3] + bv[3]);
            float4 v1 = make_float4(acc[i][4] + bv[4], acc[i][5] + bv[5],
                                    acc[i][6] + bv[6], acc[i][7] + bv[7]);
            *(float4*)(orow + 0) = v0;
            *(float4*)(orow + 4) = v1;
        }
    }
}

// ---------------------------------------------------------------------------
// Zero g_h1 (float4 stores)
// ---------------------------------------------------------------------------
__global__ void zero_h1_kernel() {
    size_t i = (size_t)blockIdx.x * blockDim.x + threadIdx.x;
    size_t n = (size_t)N_NODES * HID / 4;
    if (i < n) ((float4*)g_h1)[i] = make_float4(0.f, 0.f, 0.f, 0.f);
}

// ---------------------------------------------------------------------------
// SpMM1: g_h1[row] += val * g_h0[col], 128-wide.  One warp per edge,
// each lane handles a float4 chunk.  (ReLU applied later in gemm2 load.)
// ---------------------------------------------------------------------------
__global__ __launch_bounds__(256) void spmm1_kernel(const int* __restrict__ erow,
                                                    const int* __restrict__ ecol,
                                                    const float* __restrict__ eval,
                                                    int E) {
    unsigned t = blockIdx.x * 256u + threadIdx.x;
    unsigned e = t >> 5;
    if (e >= (unsigned)E) return;
    int lane = t & 31;
    int c = ecol[e];
    int r = erow[e];
    float v = eval[e];
    float4 h = ((const float4*)(g_h0 + (size_t)c * HID))[lane];
    float* o = g_h1 + (size_t)r * HID + lane * 4;
    atomicAdd(o + 0, v * h.x);
    atomicAdd(o + 1, v * h.y);
    atomicAdd(o + 2, v * h.z);
    atomicAdd(o + 3, v * h.w);
}

// ---------------------------------------------------------------------------
// GEMM2 + fused ReLU: g_h2 = relu(g_h1) @ W2 + b2.  M=100000, K=128, N=32.
// One thread per row; W2+b2 staged in shared memory.
// ---------------------------------------------------------------------------
__global__ __launch_bounds__(256) void gemm2_kernel(const float* __restrict__ W2,
                                                    const float* __restrict__ b2) {
    __shared__ float Ws[HID * OUT_DIM];  // 16 KB, layout [k][n]
    __shared__ float bs[OUT_DIM];
    for (int i = threadIdx.x; i < HID * OUT_DIM; i += 256) Ws[i] = W2[i];
    if (threadIdx.x < OUT_DIM) bs[threadIdx.x] = b2[threadIdx.x];
    __syncthreads();

    int r = blockIdx.x * 256 + threadIdx.x;
    if (r >= N_NODES) return;

    float acc[OUT_DIM];
#pragma unroll
    for (int n = 0; n < OUT_DIM; n++) acc[n] = bs[n];

    const float4* hrow = (const float4*)(g_h1 + (size_t)r * HID);
#pragma unroll 4
    for (int k4 = 0; k4 < HID / 4; k4++) {
        float4 h = hrow[k4];
        h.x = fmaxf(h.x, 0.f);
        h.y = fmaxf(h.y, 0.f);
        h.z = fmaxf(h.z, 0.f);
        h.w = fmaxf(h.w, 0.f);
        const float* w0 = Ws + (k4 * 4) * OUT_DIM;
#pragma unroll
        for (int n = 0; n < OUT_DIM; n++) {
            acc[n] += h.x * w0[n] + h.y * w0[OUT_DIM + n] +
                      h.z * w0[2 * OUT_DIM + n] + h.w * w0[3 * OUT_DIM + n];
        }
    }

    float* o = g_h2 + (size_t)r * OUT_DIM;
#pragma unroll
    for (int n = 0; n < OUT_DIM; n += 4)
        *(float4*)(o + n) = make_float4(acc[n], acc[n + 1], acc[n + 2], acc[n + 3]);
}

// ---------------------------------------------------------------------------
// SpMM2: out[row] += val * g_h2[col], 32-wide.  8 threads per edge.
// ---------------------------------------------------------------------------
__global__ __launch_bounds__(256) void spmm2_kernel(const int* __restrict__ erow,
                                                    const int* __restrict__ ecol,
                                                    const float* __restrict__ eval,
                                                    float* __restrict__ out,
                                                    int E) {
    unsigned t = blockIdx.x * 256u + threadIdx.x;
    unsigned e = t >> 3;
    if (e >= (unsigned)E) return;
    int lane = t & 7;
    int c = ecol[e];
    int r = erow[e];
    float v = eval[e];
    float4 h = ((const float4*)(g_h2 + (size_t)c * OUT_DIM))[lane];
    float* o = out + (size_t)r * OUT_DIM + lane * 4;
    atomicAdd(o + 0, v * h.x);
    atomicAdd(o + 1, v * h.y);
    atomicAdd(o + 2, v * h.z);
    atomicAdd(o + 3, v * h.w);
}

// ---------------------------------------------------------------------------
// Launch
// ---------------------------------------------------------------------------
extern "C" void kernel_launch(void* const* d_in, const int* in_sizes, int n_in,
                              void* d_out, int out_size) {
    const float* x    = (const float*)d_in[0];
    const int*   erow = (const int*)d_in[1];
    const int*   ecol = (const int*)d_in[2];
    const float* eval = (const float*)d_in[3];
    const float* W1   = (const float*)d_in[4];
    const float* b1   = (const float*)d_in[5];
    const float* W2   = (const float*)d_in[6];
    const float* b2   = (const float*)d_in[7];
    float* out = (float*)d_out;
    const int E = in_sizes[1];

    // GEMM1: h0 = x @ W1 + b1
    gemm1_kernel<<<(N_NODES + 127) / 128, 256>>>(x, W1, b1);

    // zero h1, then SpMM1 (128-wide scatter-add)
    {
        int n4 = N_NODES * HID / 4;
        zero_h1_kernel<<<(n4 + 255) / 256, 256>>>();
    }
    {
        long long threads = (long long)E * 32;
        int grid = (int)((threads + 255) / 256);
        spmm1_kernel<<<grid, 256>>>(erow, ecol, eval, E);
    }

    // GEMM2 (+ReLU): h2 = relu(h1) @ W2 + b2
    gemm2_kernel<<<(N_NODES + 255) / 256, 256>>>(W2, b2);

    // zero out (poisoned by harness), then SpMM2 (32-wide scatter-add)
    cudaMemsetAsync(out, 0, (size_t)N_NODES * OUT_DIM * sizeof(float), 0);
    {
        long long threads = (long long)E * 8;
        int grid = (int)((threads + 255) / 256);
        spmm2_kernel<<<grid, 256>>>(erow, ecol, eval, out, E);
    }
}

// round 2
// speedup vs baseline: 2.6427x; 2.6427x over previous
#include <cuda_runtime.h>
#include <cuda_bf16.h>

#define N_NODES 100000
#define IN_DIM  256
#define HID     128
#define OUT_DIM 32
#define E_MAX   1600000

// ---------------- device scratch ----------------
__device__ float g_h0[(size_t)N_NODES * HID];        // x@W1+b1
__device__ float g_h2[(size_t)N_NODES * OUT_DIM];    // relu(A@h0)@W2+b2
__device__ int   g_cnt[N_NODES];
__device__ int   g_rowptr[N_NODES + 1];
__device__ int   g_cur[N_NODES];
__device__ int   g_bsum[128];
__device__ int   g_bsumx[128];
__device__ int2  g_cedge[E_MAX];                     // packed {col, val_bits}

// ---------------------------------------------------------------------------
// tf32 helpers
// ---------------------------------------------------------------------------
__device__ __forceinline__ unsigned f2tf32(float f) {
    unsigned u;
    asm("cvt.rna.tf32.f32 %0, %1;" : "=r"(u) : "f"(f));
    return u;
}

__device__ __forceinline__ void mma_tf32(float* d, const unsigned* a, const unsigned* b) {
    asm volatile(
        "mma.sync.aligned.m16n8k8.row.col.f32.tf32.tf32.f32 "
        "{%0,%1,%2,%3}, {%4,%5,%6,%7}, {%8,%9}, {%0,%1,%2,%3};\n"
        : "+f"(d[0]), "+f"(d[1]), "+f"(d[2]), "+f"(d[3])
        : "r"(a[0]), "r"(a[1]), "r"(a[2]), "r"(a[3]), "r"(b[0]), "r"(b[1]));
}

// ---------------------------------------------------------------------------
// GEMM1 (tf32 tensor cores): g_h0 = x @ W1 + b1.  M=100000, K=256, N=128.
// 128x128 block tile, BK=32, 256 threads (8 warps in 2x4), 64x32 per warp.
// ---------------------------------------------------------------------------
#define BK 32
__global__ __launch_bounds__(256) void gemm1_mma_kernel(const float* __restrict__ X,
                                                        const float* __restrict__ W,
                                                        const float* __restrict__ bias) {
    __shared__ unsigned As[128][BK + 4];   // pad 4 -> conflict-free A frag loads
    __shared__ unsigned Bs[BK][HID + 8];   // pad 8 -> conflict-free B frag loads

    const int tid  = threadIdx.x;
    const int wid  = tid >> 5;
    const int lane = tid & 31;
    const int g    = lane >> 2;     // group id 0..7
    const int t    = lane & 3;      // thread-in-group 0..3
    const int wm   = wid >> 2;      // 0..1  -> 64 rows
    const int wn   = wid & 3;       // 0..3  -> 32 cols
    const int block_m = blockIdx.x * 128;

    float acc[4][4][4];
#pragma unroll
    for (int mi = 0; mi < 4; mi++)
#pragma unroll
        for (int ni = 0; ni < 4; ni++)
#pragma unroll
            for (int q = 0; q < 4; q++) acc[mi][ni][q] = 0.0f;

    // A load mapping: 128 rows x 8 float4-cols, 4 rounds of 32 rows
    const int ar = tid >> 3;          // 0..31 (+32*i)
    const int ac4 = (tid & 7) * 4;    // col in floats (0..28)
    // B load mapping: 8 k-rows x 32 float4-cols, 4 rounds
    const int bk = tid >> 5;          // 0..7 (+8*i)
    const int bn4 = (tid & 31) * 4;

    for (int k0 = 0; k0 < IN_DIM; k0 += BK) {
#pragma unroll
        for (int i = 0; i < 4; i++) {
            int r = ar + 32 * i;
            int m = block_m + r;
            float4 v = make_float4(0.f, 0.f, 0.f, 0.f);
            if (m < N_NODES) v = *(const float4*)(X + (size_t)m * IN_DIM + k0 + ac4);
            As[r][ac4 + 0] = f2tf32(v.x);
            As[r][ac4 + 1] = f2tf32(v.y);
            As[r][ac4 + 2] = f2tf32(v.z);
            As[r][ac4 + 3] = f2tf32(v.w);
        }
#pragma unroll
        for (int i = 0; i < 4; i++) {
            int k = bk + 8 * i;
            float4 v = *(const float4*)(W + (size_t)(k0 + k) * HID + bn4);
            Bs[k][bn4 + 0] = f2tf32(v.x);
            Bs[k][bn4 + 1] = f2tf32(v.y);
            Bs[k][bn4 + 2] = f2tf32(v.z);
            Bs[k][bn4 + 3] = f2tf32(v.w);
        }
        __syncthreads();

#pragma unroll
        for (int kk = 0; kk < BK; kk += 8) {
            unsigned af[4][4];
            unsigned bf[4][2];
#pragma unroll
            for (int mi = 0; mi < 4; mi++) {
                int m = wm * 64 + mi * 16 + g;
                af[mi][0] = As[m][kk + t];
                af[mi][1] = As[m + 8][kk + t];
                af[mi][2] = As[m][kk + t + 4];
                af[mi][3] = As[m + 8][kk + t + 4];
            }
#pragma unroll
            for (int ni = 0; ni < 4; ni++) {
                int n = wn * 32 + ni * 8 + g;
                bf[ni][0] = Bs[kk + t][n];
                bf[ni][1] = Bs[kk + t + 4][n];
            }
#pragma unroll
            for (int mi = 0; mi < 4; mi++)
#pragma unroll
                for (int ni = 0; ni < 4; ni++)
                    mma_tf32(acc[mi][ni], af[mi], bf[ni]);
        }
        __syncthreads();
    }

    // epilogue: add bias, store float2 pairs
#pragma unroll
    for (int ni = 0; ni < 4; ni++) {
        int n = wn * 32 + ni * 8 + 2 * t;
        float b0 = bias[n], b1 = bias[n + 1];
#pragma unroll
        for (int mi = 0; mi < 4; mi++) {
            int r0 = block_m + wm * 64 + mi * 16 + g;
            int r1 = r0 + 8;
            if (r0 < N_NODES)
                *(float2*)(g_h0 + (size_t)r0 * HID + n) =
                    make_float2(acc[mi][ni][0] + b0, acc[mi][ni][1] + b1);
            if (r1 < N_NODES)
                *(float2*)(g_h0 + (size_t)r1 * HID + n) =
                    make_float2(acc[mi][ni][2] + b0, acc[mi][ni][3] + b1);
        }
    }
}

// ---------------------------------------------------------------------------
// CSR build
// ---------------------------------------------------------------------------
__global__ void zero_cnt_kernel() {
    int i = blockIdx.x * 256 + threadIdx.x;
    if (i < N_NODES) g_cnt[i] = 0;
}

__global__ void csr_count_kernel(const int* __restrict__ erow, int E) {
    int e = blockIdx.x * 256 + threadIdx.x;
    if (e < E) atomicAdd(&g_cnt[erow[e]], 1);
}

// 1024-element blocks, Hillis-Steele inclusive scan -> exclusive partials
__global__ __launch_bounds__(1024) void scan1_kernel() {
    __shared__ int s[1024];
    int t = threadIdx.x;
    int i = blockIdx.x * 1024 + t;
    int v = (i < N_NODES) ? g_cnt[i] : 0;
    s[t] = v;
    for (int off = 1; off < 1024; off <<= 1) {
        __syncthreads();
        int tmp = (t >= off) ? s[t - off] : 0;
        __syncthreads();
        s[t] += tmp;
    }
    if (i < N_NODES) g_rowptr[i] = s[t] - v;      // exclusive partial
    if (t == 1023) g_bsum[blockIdx.x] = s[1023];
}

__global__ void scan2_kernel(int nb, int E) {
    if (threadIdx.x == 0) {
        int run = 0;
        for (int j = 0; j < nb; j++) { g_bsumx[j] = run; run += g_bsum[j]; }
        g_rowptr[N_NODES] = E;
    }
}

__global__ void scan3_kernel() {
    int i = blockIdx.x * 256 + threadIdx.x;
    if (i < N_NODES) {
        int v = g_rowptr[i] + g_bsumx[i >> 10];
        g_rowptr[i] = v;
        g_cur[i] = v;
    }
}

__global__ void csr_scatter_kernel(const int* __restrict__ erow,
                                   const int* __restrict__ ecol,
                                   const float* __restrict__ eval, int E) {
    int e = blockIdx.x * 256 + threadIdx.x;
    if (e < E) {
        int r = erow[e];
        int idx = atomicAdd(&g_cur[r], 1);
        g_cedge[idx] = make_int2(ecol[e], __float_as_int(eval[e]));
    }
}

// ---------------------------------------------------------------------------
// Fused SpMM1 + ReLU + GEMM2: per row r (one warp):
//   h1 = sum_e val*h0[col] (128-wide, 4 floats/lane), relu,
//   h2[r][lane] = b2[lane] + sum_k relu(h1)[k] * W2[k][lane]
// ---------------------------------------------------------------------------
__global__ __launch_bounds__(256) void spmm1_fused_kernel(const float* __restrict__ W2,
                                                          const float* __restrict__ b2) {
    __shared__ float W2s[HID * OUT_DIM];   // [k][n]
    __shared__ float b2s[OUT_DIM];
    for (int i = threadIdx.x; i < HID * OUT_DIM; i += 256) W2s[i] = W2[i];
    if (threadIdx.x < OUT_DIM) b2s[threadIdx.x] = b2[threadIdx.x];
    __syncthreads();

    const int wid = threadIdx.x >> 5;
    const int lane = threadIdx.x & 31;
    const int r = blockIdx.x * 8 + wid;
    if (r >= N_NODES) return;

    const int s0 = g_rowptr[r];
    const int s1 = g_rowptr[r + 1];

    float4 acc = make_float4(0.f, 0.f, 0.f, 0.f);
    for (int base = s0; base < s1; base += 32) {
        int cnt = min(32, s1 - base);
        int2 pk = make_int2(0, 0);
        if (lane < cnt) pk = g_cedge[base + lane];
        int j = 0;
        for (; j + 4 <= cnt; j += 4) {
            int c0 = __shfl_sync(0xffffffffu, pk.x, j + 0);
            int c1 = __shfl_sync(0xffffffffu, pk.x, j + 1);
            int c2 = __shfl_sync(0xffffffffu, pk.x, j + 2);
            int c3 = __shfl_sync(0xffffffffu, pk.x, j + 3);
            float v0 = __int_as_float(__shfl_sync(0xffffffffu, pk.y, j + 0));
            float v1 = __int_as_float(__shfl_sync(0xffffffffu, pk.y, j + 1));
            float v2 = __int_as_float(__shfl_sync(0xffffffffu, pk.y, j + 2));
            float v3 = __int_as_float(__shfl_sync(0xffffffffu, pk.y, j + 3));
            float4 f0 = ((const float4*)(g_h0 + (size_t)c0 * HID))[lane];
            float4 f1 = ((const float4*)(g_h0 + (size_t)c1 * HID))[lane];
            float4 f2 = ((const float4*)(g_h0 + (size_t)c2 * HID))[lane];
            float4 f3 = ((const float4*)(g_h0 + (size_t)c3 * HID))[lane];
            acc.x += v0 * f0.x + v1 * f1.x + v2 * f2.x + v3 * f3.x;
            acc.y += v0 * f0.y + v1 * f1.y + v2 * f2.y + v3 * f3.y;
            acc.z += v0 * f0.z + v1 * f1.z + v2 * f2.z + v3 * f3.z;
            acc.w += v0 * f0.w + v1 * f1.w + v2 * f2.w + v3 * f3.w;
        }
        for (; j < cnt; j++) {
            int c = __shfl_sync(0xffffffffu, pk.x, j);
            float v = __int_as_float(__shfl_sync(0xffffffffu, pk.y, j));
            float4 f = ((const float4*)(g_h0 + (size_t)c * HID))[lane];
            acc.x += v * f.x; acc.y += v * f.y; acc.z += v * f.z; acc.w += v * f.w;
        }
    }

    // ReLU
    float h[4];
    h[0] = fmaxf(acc.x, 0.f);
    h[1] = fmaxf(acc.y, 0.f);
    h[2] = fmaxf(acc.z, 0.f);
    h[3] = fmaxf(acc.w, 0.f);

    // mat-vec: lane = output col
    float o = b2s[lane];
#pragma unroll
    for (int k = 0; k < HID; k++) {
        float hk = __shfl_sync(0xffffffffu, h[k & 3], k >> 2);
        o += hk * W2s[k * OUT_DIM + lane];
    }
    g_h2[(size_t)r * OUT_DIM + lane] = o;
}

// ---------------------------------------------------------------------------
// SpMM2: out[r][lane] = sum_e val * h2[col][lane]   (one warp per row)
// ---------------------------------------------------------------------------
__global__ __launch_bounds__(256) void spmm2_csr_kernel(float* __restrict__ out) {
    const int wid = threadIdx.x >> 5;
    const int lane = threadIdx.x & 31;
    const int r = blockIdx.x * 8 + wid;
    if (r >= N_NODES) return;

    const int s0 = g_rowptr[r];
    const int s1 = g_rowptr[r + 1];

    float acc = 0.f;
    for (int base = s0; base < s1; base += 32) {
        int cnt = min(32, s1 - base);
        int2 pk = make_int2(0, 0);
        if (lane < cnt) pk = g_cedge[base + lane];
        int j = 0;
        for (; j + 4 <= cnt; j += 4) {
            int c0 = __shfl_sync(0xffffffffu, pk.x, j + 0);
            int c1 = __shfl_sync(0xffffffffu, pk.x, j + 1);
            int c2 = __shfl_sync(0xffffffffu, pk.x, j + 2);
            int c3 = __shfl_sync(0xffffffffu, pk.x, j + 3);
            float v0 = __int_as_float(__shfl_sync(0xffffffffu, pk.y, j + 0));
            float v1 = __int_as_float(__shfl_sync(0xffffffffu, pk.y, j + 1));
            float v2 = __int_as_float(__shfl_sync(0xffffffffu, pk.y, j + 2));
            float v3 = __int_as_float(__shfl_sync(0xffffffffu, pk.y, j + 3));
            float f0 = g_h2[(size_t)c0 * OUT_DIM + lane];
            float f1 = g_h2[(size_t)c1 * OUT_DIM + lane];
            float f2 = g_h2[(size_t)c2 * OUT_DIM + lane];
            float f3 = g_h2[(size_t)c3 * OUT_DIM + lane];
            acc += v0 * f0 + v1 * f1 + v2 * f2 + v3 * f3;
        }
        for (; j < cnt; j++) {
            int c = __shfl_sync(0xffffffffu, pk.x, j);
            float v = __int_as_float(__shfl_sync(0xffffffffu, pk.y, j));
            acc += v * g_h2[(size_t)c * OUT_DIM + lane];
        }
    }
    out[(size_t)r * OUT_DIM + lane] = acc;
}

// ---------------------------------------------------------------------------
// Launch
// ---------------------------------------------------------------------------
extern "C" void kernel_launch(void* const* d_in, const int* in_sizes, int n_in,
                              void* d_out, int out_size) {
    const float* x    = (const float*)d_in[0];
    const int*   erow = (const int*)d_in[1];
    const int*   ecol = (const int*)d_in[2];
    const float* eval = (const float*)d_in[3];
    const float* W1   = (const float*)d_in[4];
    const float* b1   = (const float*)d_in[5];
    const float* W2   = (const float*)d_in[6];
    const float* b2   = (const float*)d_in[7];
    float* out = (float*)d_out;
    const int E = in_sizes[1];

    const int nb_nodes = (N_NODES + 255) / 256;
    const int nb_edges = (E + 255) / 256;
    const int nb_scan  = (N_NODES + 1023) / 1024;
    const int nb_rows8 = (N_NODES + 7) / 8;

    // CSR build (independent of gemm1; same stream keeps ordering simple)
    zero_cnt_kernel<<<nb_nodes, 256>>>();
    csr_count_kernel<<<nb_edges, 256>>>(erow, E);
    scan1_kernel<<<nb_scan, 1024>>>();
    scan2_kernel<<<1, 32>>>(nb_scan, E);
    scan3_kernel<<<nb_nodes, 256>>>();
    csr_scatter_kernel<<<nb_edges, 256>>>(erow, ecol, eval, E);

    // GEMM1 (tf32 tensor cores)
    gemm1_mma_kernel<<<(N_NODES + 127) / 128, 256>>>(x, W1, b1);

    // SpMM1 + ReLU + GEMM2 fused
    spmm1_fused_kernel<<<nb_rows8, 256>>>(W2, b2);

    // SpMM2
    spmm2_csr_kernel<<<nb_rows8, 256>>>(out);
}

// round 3
// speedup vs baseline: 2.8288x; 1.0704x over previous
#include <cuda_runtime.h>
#include <cuda_fp16.h>
#include <cuda_bf16.h>

#define N_NODES 100000
#define IN_DIM  256
#define HID     128
#define OUT_DIM 32
#define E_MAX   1600000

// ---------------- device scratch ----------------
__device__ __half g_h0h[(size_t)N_NODES * HID];       // fp16 x@W1+b1
__device__ __half g_h2h[(size_t)N_NODES * OUT_DIM];   // fp16 relu(A@h0)@W2+b2
__device__ int   g_cnt[N_NODES];
__device__ int   g_rowptr[N_NODES + 1];
__device__ int   g_cur[N_NODES];
__device__ int   g_bsum[128];
__device__ int   g_bsumx[128];
__device__ int2  g_cedge[E_MAX];                      // packed {col, val_bits}

// ---------------------------------------------------------------------------
// tf32 helpers
// ---------------------------------------------------------------------------
__device__ __forceinline__ unsigned f2tf32(float f) {
    unsigned u;
    asm("cvt.rna.tf32.f32 %0, %1;" : "=r"(u) : "f"(f));
    return u;
}

__device__ __forceinline__ void mma_tf32(float* d, const unsigned* a, const unsigned* b) {
    asm volatile(
        "mma.sync.aligned.m16n8k8.row.col.f32.tf32.tf32.f32 "
        "{%0,%1,%2,%3}, {%4,%5,%6,%7}, {%8,%9}, {%0,%1,%2,%3};\n"
        : "+f"(d[0]), "+f"(d[1]), "+f"(d[2]), "+f"(d[3])
        : "r"(a[0]), "r"(a[1]), "r"(a[2]), "r"(a[3]), "r"(b[0]), "r"(b[1]));
}

// ---------------------------------------------------------------------------
// GEMM1 (tf32 tensor cores): g_h0h = half(x @ W1 + b1).  M=100000, K=256, N=128.
// 128x128 block tile, BK=32, 256 threads (8 warps in 2x4), 64x32 per warp.
// ---------------------------------------------------------------------------
#define BK 32
__global__ __launch_bounds__(256) void gemm1_mma_kernel(const float* __restrict__ X,
                                                        const float* __restrict__ W,
                                                        const float* __restrict__ bias) {
    __shared__ unsigned As[128][BK + 4];
    __shared__ unsigned Bs[BK][HID + 8];

    const int tid  = threadIdx.x;
    const int wid  = tid >> 5;
    const int lane = tid & 31;
    const int g    = lane >> 2;
    const int t    = lane & 3;
    const int wm   = wid >> 2;
    const int wn   = wid & 3;
    const int block_m = blockIdx.x * 128;

    float acc[4][4][4];
#pragma unroll
    for (int mi = 0; mi < 4; mi++)
#pragma unroll
        for (int ni = 0; ni < 4; ni++)
#pragma unroll
            for (int q = 0; q < 4; q++) acc[mi][ni][q] = 0.0f;

    const int ar = tid >> 3;
    const int ac4 = (tid & 7) * 4;
    const int bk = tid >> 5;
    const int bn4 = (tid & 31) * 4;

    for (int k0 = 0; k0 < IN_DIM; k0 += BK) {
#pragma unroll
        for (int i = 0; i < 4; i++) {
            int r = ar + 32 * i;
            int m = block_m + r;
            float4 v = make_float4(0.f, 0.f, 0.f, 0.f);
            if (m < N_NODES) v = *(const float4*)(X + (size_t)m * IN_DIM + k0 + ac4);
            As[r][ac4 + 0] = f2tf32(v.x);
            As[r][ac4 + 1] = f2tf32(v.y);
            As[r][ac4 + 2] = f2tf32(v.z);
            As[r][ac4 + 3] = f2tf32(v.w);
        }
#pragma unroll
        for (int i = 0; i < 4; i++) {
            int k = bk + 8 * i;
            float4 v = *(const float4*)(W + (size_t)(k0 + k) * HID + bn4);
            Bs[k][bn4 + 0] = f2tf32(v.x);
            Bs[k][bn4 + 1] = f2tf32(v.y);
            Bs[k][bn4 + 2] = f2tf32(v.z);
            Bs[k][bn4 + 3] = f2tf32(v.w);
        }
        __syncthreads();

#pragma unroll
        for (int kk = 0; kk < BK; kk += 8) {
            unsigned af[4][4];
            unsigned bf[4][2];
#pragma unroll
            for (int mi = 0; mi < 4; mi++) {
                int m = wm * 64 + mi * 16 + g;
                af[mi][0] = As[m][kk + t];
                af[mi][1] = As[m + 8][kk + t];
                af[mi][2] = As[m][kk + t + 4];
                af[mi][3] = As[m + 8][kk + t + 4];
            }
#pragma unroll
            for (int ni = 0; ni < 4; ni++) {
                int n = wn * 32 + ni * 8 + g;
                bf[ni][0] = Bs[kk + t][n];
                bf[ni][1] = Bs[kk + t + 4][n];
            }
#pragma unroll
            for (int mi = 0; mi < 4; mi++)
#pragma unroll
                for (int ni = 0; ni < 4; ni++)
                    mma_tf32(acc[mi][ni], af[mi], bf[ni]);
        }
        __syncthreads();
    }

    // epilogue: add bias, convert to half2, store
#pragma unroll
    for (int ni = 0; ni < 4; ni++) {
        int n = wn * 32 + ni * 8 + 2 * t;
        float b0 = bias[n], b1 = bias[n + 1];
#pragma unroll
        for (int mi = 0; mi < 4; mi++) {
            int r0 = block_m + wm * 64 + mi * 16 + g;
            int r1 = r0 + 8;
            if (r0 < N_NODES)
                *(__half2*)(g_h0h + (size_t)r0 * HID + n) =
                    __floats2half2_rn(acc[mi][ni][0] + b0, acc[mi][ni][1] + b1);
            if (r1 < N_NODES)
                *(__half2*)(g_h0h + (size_t)r1 * HID + n) =
                    __floats2half2_rn(acc[mi][ni][2] + b0, acc[mi][ni][3] + b1);
        }
    }
}

// ---------------------------------------------------------------------------
// CSR build
// ---------------------------------------------------------------------------
__global__ void zero_cnt_kernel() {
    int i = blockIdx.x * 256 + threadIdx.x;
    if (i < N_NODES) g_cnt[i] = 0;
}

__global__ void csr_count_kernel(const int* __restrict__ erow, int E) {
    int e = blockIdx.x * 256 + threadIdx.x;
    if (e < E) atomicAdd(&g_cnt[erow[e]], 1);
}

__global__ __launch_bounds__(1024) void scan1_kernel() {
    __shared__ int s[1024];
    int t = threadIdx.x;
    int i = blockIdx.x * 1024 + t;
    int v = (i < N_NODES) ? g_cnt[i] : 0;
    s[t] = v;
    for (int off = 1; off < 1024; off <<= 1) {
        __syncthreads();
        int tmp = (t >= off) ? s[t - off] : 0;
        __syncthreads();
        s[t] += tmp;
    }
    if (i < N_NODES) g_rowptr[i] = s[t] - v;
    if (t == 1023) g_bsum[blockIdx.x] = s[1023];
}

// parallel scan over <=128 block sums
__global__ void scan2_kernel(int nb, int E) {
    __shared__ int s[128];
    int t = threadIdx.x;
    int v = (t < nb) ? g_bsum[t] : 0;
    s[t] = v;
    for (int off = 1; off < 128; off <<= 1) {
        __syncthreads();
        int tmp = (t >= off) ? s[t - off] : 0;
        __syncthreads();
        s[t] += tmp;
    }
    if (t < nb) g_bsumx[t] = s[t] - v;   // exclusive
    if (t == 0) g_rowptr[N_NODES] = E;
}

__global__ void scan3_kernel() {
    int i = blockIdx.x * 256 + threadIdx.x;
    if (i < N_NODES) {
        int v = g_rowptr[i] + g_bsumx[i >> 10];
        g_rowptr[i] = v;
        g_cur[i] = v;
    }
}

__global__ void csr_scatter_kernel(const int* __restrict__ erow,
                                   const int* __restrict__ ecol,
                                   const float* __restrict__ eval, int E) {
    int e = blockIdx.x * 256 + threadIdx.x;
    if (e < E) {
        int r = erow[e];
        int idx = atomicAdd(&g_cur[r], 1);
        g_cedge[idx] = make_int2(ecol[e], __float_as_int(eval[e]));
    }
}

// ---------------------------------------------------------------------------
// Fused SpMM1 + ReLU + GEMM2 (one warp per row, fp16 h0 gathers):
//   h1 = sum_e val*h0[col], relu, h2[r][lane] = b2[lane] + sum_k h1[k]*W2[k][lane]
// ---------------------------------------------------------------------------
__global__ __launch_bounds__(256) void spmm1_fused_kernel(const float* __restrict__ W2,
                                                          const float* __restrict__ b2) {
    __shared__ float W2s[HID * OUT_DIM];   // [k][n]
    __shared__ float b2s[OUT_DIM];
    for (int i = threadIdx.x; i < HID * OUT_DIM; i += 256) W2s[i] = W2[i];
    if (threadIdx.x < OUT_DIM) b2s[threadIdx.x] = b2[threadIdx.x];
    __syncthreads();

    const int wid = threadIdx.x >> 5;
    const int lane = threadIdx.x & 31;
    const int r = blockIdx.x * 8 + wid;
    if (r >= N_NODES) return;

    const int s0 = g_rowptr[r];
    const int s1 = g_rowptr[r + 1];

    float4 acc = make_float4(0.f, 0.f, 0.f, 0.f);
    for (int base = s0; base < s1; base += 32) {
        int cnt = min(32, s1 - base);
        int2 pk = make_int2(0, 0);
        if (lane < cnt) pk = g_cedge[base + lane];
        int j = 0;
        for (; j + 4 <= cnt; j += 4) {
#pragma unroll
            for (int u = 0; u < 4; u++) {
                int c = __shfl_sync(0xffffffffu, pk.x, j + u);
                float v = __int_as_float(__shfl_sync(0xffffffffu, pk.y, j + u));
                uint2 hw = ((const uint2*)(g_h0h + (size_t)c * HID))[lane];
                float2 f0 = __half22float2(*(__half2*)&hw.x);
                float2 f1 = __half22float2(*(__half2*)&hw.y);
                acc.x += v * f0.x; acc.y += v * f0.y;
                acc.z += v * f1.x; acc.w += v * f1.y;
            }
        }
        for (; j < cnt; j++) {
            int c = __shfl_sync(0xffffffffu, pk.x, j);
            float v = __int_as_float(__shfl_sync(0xffffffffu, pk.y, j));
            uint2 hw = ((const uint2*)(g_h0h + (size_t)c * HID))[lane];
            float2 f0 = __half22float2(*(__half2*)&hw.x);
            float2 f1 = __half22float2(*(__half2*)&hw.y);
            acc.x += v * f0.x; acc.y += v * f0.y;
            acc.z += v * f1.x; acc.w += v * f1.y;
        }
    }

    float h[4];
    h[0] = fmaxf(acc.x, 0.f);
    h[1] = fmaxf(acc.y, 0.f);
    h[2] = fmaxf(acc.z, 0.f);
    h[3] = fmaxf(acc.w, 0.f);

    float o = b2s[lane];
#pragma unroll
    for (int k = 0; k < HID; k++) {
        float hk = __shfl_sync(0xffffffffu, h[k & 3], k >> 2);
        o += hk * W2s[k * OUT_DIM + lane];
    }
    g_h2h[(size_t)r * OUT_DIM + lane] = __float2half_rn(o);
}

// ---------------------------------------------------------------------------
// SpMM2: out[r][lane] = sum_e val * h2[col][lane]   (one warp per row)
// ---------------------------------------------------------------------------
__global__ __launch_bounds__(256) void spmm2_csr_kernel(float* __restrict__ out) {
    const int wid = threadIdx.x >> 5;
    const int lane = threadIdx.x & 31;
    const int r = blockIdx.x * 8 + wid;
    if (r >= N_NODES) return;

    const int s0 = g_rowptr[r];
    const int s1 = g_rowptr[r + 1];

    float acc = 0.f;
    for (int base = s0; base < s1; base += 32) {
        int cnt = min(32, s1 - base);
        int2 pk = make_int2(0, 0);
        if (lane < cnt) pk = g_cedge[base + lane];
        int j = 0;
        for (; j + 4 <= cnt; j += 4) {
#pragma unroll
            for (int u = 0; u < 4; u++) {
                int c = __shfl_sync(0xffffffffu, pk.x, j + u);
                float v = __int_as_float(__shfl_sync(0xffffffffu, pk.y, j + u));
                acc += v * __half2float(g_h2h[(size_t)c * OUT_DIM + lane]);
            }
        }
        for (; j < cnt; j++) {
            int c = __shfl_sync(0xffffffffu, pk.x, j);
            float v = __int_as_float(__shfl_sync(0xffffffffu, pk.y, j));
            acc += v * __half2float(g_h2h[(size_t)c * OUT_DIM + lane]);
        }
    }
    out[(size_t)r * OUT_DIM + lane] = acc;
}

// ---------------------------------------------------------------------------
// Launch
// ---------------------------------------------------------------------------
extern "C" void kernel_launch(void* const* d_in, const int* in_sizes, int n_in,
                              void* d_out, int out_size) {
    const float* x    = (const float*)d_in[0];
    const int*   erow = (const int*)d_in[1];
    const int*   ecol = (const int*)d_in[2];
    const float* eval = (const float*)d_in[3];
    const float* W1   = (const float*)d_in[4];
    const float* b1   = (const float*)d_in[5];
    const float* W2   = (const float*)d_in[6];
    const float* b2   = (const float*)d_in[7];
    float* out = (float*)d_out;
    const int E = in_sizes[1];

    const int nb_nodes = (N_NODES + 255) / 256;
    const int nb_edges = (E + 255) / 256;
    const int nb_scan  = (N_NODES + 1023) / 1024;
    const int nb_rows8 = (N_NODES + 7) / 8;

    // CSR build
    zero_cnt_kernel<<<nb_nodes, 256>>>();
    csr_count_kernel<<<nb_edges, 256>>>(erow, E);
    scan1_kernel<<<nb_scan, 1024>>>();
    scan2_kernel<<<1, 128>>>(nb_scan, E);
    scan3_kernel<<<nb_nodes, 256>>>();
    csr_scatter_kernel<<<nb_edges, 256>>>(erow, ecol, eval, E);

    // GEMM1 (tf32 tensor cores, fp16 output)
    gemm1_mma_kernel<<<(N_NODES + 127) / 128, 256>>>(x, W1, b1);

    // SpMM1 + ReLU + GEMM2 fused
    spmm1_fused_kernel<<<nb_rows8, 256>>>(W2, b2);

    // SpMM2
    spmm2_csr_kernel<<<nb_rows8, 256>>>(out);
}

// round 5
// speedup vs baseline: 2.9883x; 1.0564x over previous
#include <cuda_runtime.h>
#include <cuda_fp16.h>
#include <cuda_bf16.h>

#define N_NODES 100000
#define IN_DIM  256
#define HID     128
#define OUT_DIM 32
#define E_MAX   1600000

// ---------------- device scratch ----------------
__device__ __half g_h0h[(size_t)N_NODES * HID];       // fp16 x@W1+b1
__device__ __half g_h2h[(size_t)N_NODES * OUT_DIM];   // fp16 relu(A@h0)@W2+b2
__device__ int   g_cnt[N_NODES];
__device__ int   g_rowptr[N_NODES + 1];
__device__ int   g_cur[N_NODES];
__device__ int   g_bsum[128];
__device__ int   g_bsumx[128];
__device__ int2  g_cedge[E_MAX];                      // packed {col, val_bits}

// ---------------------------------------------------------------------------
// tf32 helpers
// ---------------------------------------------------------------------------
__device__ __forceinline__ unsigned f2tf32(float f) {
    unsigned u;
    asm("cvt.rna.tf32.f32 %0, %1;" : "=r"(u) : "f"(f));
    return u;
}

__device__ __forceinline__ void mma_tf32(float* d, const unsigned* a, const unsigned* b) {
    asm volatile(
        "mma.sync.aligned.m16n8k8.row.col.f32.tf32.tf32.f32 "
        "{%0,%1,%2,%3}, {%4,%5,%6,%7}, {%8,%9}, {%0,%1,%2,%3};\n"
        : "+f"(d[0]), "+f"(d[1]), "+f"(d[2]), "+f"(d[3])
        : "r"(a[0]), "r"(a[1]), "r"(a[2]), "r"(a[3]), "r"(b[0]), "r"(b[1]));
}

// ---------------------------------------------------------------------------
// GEMM1 (tf32 tensor cores): g_h0h = half(x @ W1 + b1)
// ---------------------------------------------------------------------------
#define BK 32
__global__ __launch_bounds__(256) void gemm1_mma_kernel(const float* __restrict__ X,
                                                        const float* __restrict__ W,
                                                        const float* __restrict__ bias) {
    __shared__ unsigned As[128][BK + 4];
    __shared__ unsigned Bs[BK][HID + 8];

    const int tid  = threadIdx.x;
    const int wid  = tid >> 5;
    const int lane = tid & 31;
    const int g    = lane >> 2;
    const int t    = lane & 3;
    const int wm   = wid >> 2;
    const int wn   = wid & 3;
    const int block_m = blockIdx.x * 128;

    float acc[4][4][4];
#pragma unroll
    for (int mi = 0; mi < 4; mi++)
#pragma unroll
        for (int ni = 0; ni < 4; ni++)
#pragma unroll
            for (int q = 0; q < 4; q++) acc[mi][ni][q] = 0.0f;

    const int ar = tid >> 3;
    const int ac4 = (tid & 7) * 4;
    const int bk = tid >> 5;
    const int bn4 = (tid & 31) * 4;

    for (int k0 = 0; k0 < IN_DIM; k0 += BK) {
#pragma unroll
        for (int i = 0; i < 4; i++) {
            int r = ar + 32 * i;
            int m = block_m + r;
            float4 v = make_float4(0.f, 0.f, 0.f, 0.f);
            if (m < N_NODES) v = *(const float4*)(X + (size_t)m * IN_DIM + k0 + ac4);
            As[r][ac4 + 0] = f2tf32(v.x);
            As[r][ac4 + 1] = f2tf32(v.y);
            As[r][ac4 + 2] = f2tf32(v.z);
            As[r][ac4 + 3] = f2tf32(v.w);
        }
#pragma unroll
        for (int i = 0; i < 4; i++) {
            int k = bk + 8 * i;
            float4 v = *(const float4*)(W + (size_t)(k0 + k) * HID + bn4);
            Bs[k][bn4 + 0] = f2tf32(v.x);
            Bs[k][bn4 + 1] = f2tf32(v.y);
            Bs[k][bn4 + 2] = f2tf32(v.z);
            Bs[k][bn4 + 3] = f2tf32(v.w);
        }
        __syncthreads();

#pragma unroll
        for (int kk = 0; kk < BK; kk += 8) {
            unsigned af[4][4];
            unsigned bf[4][2];
#pragma unroll
            for (int mi = 0; mi < 4; mi++) {
                int m = wm * 64 + mi * 16 + g;
                af[mi][0] = As[m][kk + t];
                af[mi][1] = As[m + 8][kk + t];
                af[mi][2] = As[m][kk + t + 4];
                af[mi][3] = As[m + 8][kk + t + 4];
            }
#pragma unroll
            for (int ni = 0; ni < 4; ni++) {
                int n = wn * 32 + ni * 8 + g;
                bf[ni][0] = Bs[kk + t][n];
                bf[ni][1] = Bs[kk + t + 4][n];
            }
#pragma unroll
            for (int mi = 0; mi < 4; mi++)
#pragma unroll
                for (int ni = 0; ni < 4; ni++)
                    mma_tf32(acc[mi][ni], af[mi], bf[ni]);
        }
        __syncthreads();
    }

#pragma unroll
    for (int ni = 0; ni < 4; ni++) {
        int n = wn * 32 + ni * 8 + 2 * t;
        float b0 = bias[n], b1 = bias[n + 1];
#pragma unroll
        for (int mi = 0; mi < 4; mi++) {
            int r0 = block_m + wm * 64 + mi * 16 + g;
            int r1 = r0 + 8;
            if (r0 < N_NODES)
                *(__half2*)(g_h0h + (size_t)r0 * HID + n) =
                    __floats2half2_rn(acc[mi][ni][0] + b0, acc[mi][ni][1] + b1);
            if (r1 < N_NODES)
                *(__half2*)(g_h0h + (size_t)r1 * HID + n) =
                    __floats2half2_rn(acc[mi][ni][2] + b0, acc[mi][ni][3] + b1);
        }
    }
}

// ---------------------------------------------------------------------------
// CSR build
// ---------------------------------------------------------------------------
__global__ void zero_cnt_kernel() {
    int i = blockIdx.x * 256 + threadIdx.x;
    if (i < N_NODES) g_cnt[i] = 0;
}

__global__ void csr_count_kernel(const int* __restrict__ erow, int E) {
    int e = blockIdx.x * 256 + threadIdx.x;
    if (e < E) atomicAdd(&g_cnt[erow[e]], 1);
}

__global__ __launch_bounds__(1024) void scan1_kernel() {
    __shared__ int s[1024];
    int t = threadIdx.x;
    int i = blockIdx.x * 1024 + t;
    int v = (i < N_NODES) ? g_cnt[i] : 0;
    s[t] = v;
    for (int off = 1; off < 1024; off <<= 1) {
        __syncthreads();
        int tmp = (t >= off) ? s[t - off] : 0;
        __syncthreads();
        s[t] += tmp;
    }
    if (i < N_NODES) g_rowptr[i] = s[t] - v;
    if (t == 1023) g_bsum[blockIdx.x] = s[1023];
}

__global__ void scan2_kernel(int nb, int E) {
    __shared__ int s[128];
    int t = threadIdx.x;
    int v = (t < nb) ? g_bsum[t] : 0;
    s[t] = v;
    for (int off = 1; off < 128; off <<= 1) {
        __syncthreads();
        int tmp = (t >= off) ? s[t - off] : 0;
        __syncthreads();
        s[t] += tmp;
    }
    if (t < nb) g_bsumx[t] = s[t] - v;
    if (t == 0) g_rowptr[N_NODES] = E;
}

__global__ void scan3_kernel() {
    int i = blockIdx.x * 256 + threadIdx.x;
    if (i < N_NODES) {
        int v = g_rowptr[i] + g_bsumx[i >> 10];
        g_rowptr[i] = v;
        g_cur[i] = v;
    }
}

__global__ void csr_scatter_kernel(const int* __restrict__ erow,
                                   const int* __restrict__ ecol,
                                   const float* __restrict__ eval, int E) {
    int e = blockIdx.x * 256 + threadIdx.x;
    if (e < E) {
        int r = erow[e];
        int idx = atomicAdd(&g_cur[r], 1);
        g_cedge[idx] = make_int2(ecol[e], __float_as_int(eval[e]));
    }
}

// ---------------------------------------------------------------------------
// Fused SpMM1 + ReLU + GEMM2.  One warp per row; 16 lanes cover the 128-wide
// row (uint4 = 8 halves each); the two 16-lane halves process alternating
// edges.  ALL shfls are warp-convergent (clamped source lane + zeroed weight
// for out-of-range edges).
// ---------------------------------------------------------------------------
__global__ __launch_bounds__(256) void spmm1_fused_kernel(const float* __restrict__ W2,
                                                          const float* __restrict__ b2) {
    __shared__ float W2s[HID * OUT_DIM];   // [k][n]
    __shared__ float b2s[OUT_DIM];
    for (int i = threadIdx.x; i < HID * OUT_DIM; i += 256) W2s[i] = W2[i];
    if (threadIdx.x < OUT_DIM) b2s[threadIdx.x] = b2[threadIdx.x];
    __syncthreads();

    const int wid  = threadIdx.x >> 5;
    const int lane = threadIdx.x & 31;
    const int half = lane >> 4;       // edge parity
    const int l16  = lane & 15;       // column-chunk id (8 halves each)
    const int r = blockIdx.x * 8 + wid;
    if (r >= N_NODES) return;

    const int s0 = g_rowptr[r];
    const int s1 = g_rowptr[r + 1];

    float acc[8];
#pragma unroll
    for (int i = 0; i < 8; i++) acc[i] = 0.f;

    for (int base = s0; base < s1; base += 32) {
        int cnt = min(32, s1 - base);
        int2 pk = make_int2(0, 0);
        if (lane < cnt) pk = g_cedge[base + lane];

        int j = 0;
        for (; j + 8 <= cnt; j += 8) {
#pragma unroll
            for (int u = 0; u < 4; u++) {
                int e = j + 2 * u + half;
                int c = __shfl_sync(0xffffffffu, pk.x, e);
                float v = __int_as_float(__shfl_sync(0xffffffffu, pk.y, e));
                uint4 hw = ((const uint4*)(g_h0h + (size_t)c * HID))[l16];
                float2 f0 = __half22float2(*(__half2*)&hw.x);
                float2 f1 = __half22float2(*(__half2*)&hw.y);
                float2 f2 = __half22float2(*(__half2*)&hw.z);
                float2 f3 = __half22float2(*(__half2*)&hw.w);
                acc[0] += v * f0.x; acc[1] += v * f0.y;
                acc[2] += v * f1.x; acc[3] += v * f1.y;
                acc[4] += v * f2.x; acc[5] += v * f2.y;
                acc[6] += v * f3.x; acc[7] += v * f3.y;
            }
        }
        // convergent tail: clamp source lane, zero weight for e >= cnt
        for (; j < cnt; j += 2) {
            int e = j + half;
            int esafe = (e < cnt) ? e : (cnt - 1);
            int c = __shfl_sync(0xffffffffu, pk.x, esafe);
            float v = __int_as_float(__shfl_sync(0xffffffffu, pk.y, esafe));
            if (e >= cnt) v = 0.f;
            uint4 hw = ((const uint4*)(g_h0h + (size_t)c * HID))[l16];
            float2 f0 = __half22float2(*(__half2*)&hw.x);
            float2 f1 = __half22float2(*(__half2*)&hw.y);
            float2 f2 = __half22float2(*(__half2*)&hw.z);
            float2 f3 = __half22float2(*(__half2*)&hw.w);
            acc[0] += v * f0.x; acc[1] += v * f0.y;
            acc[2] += v * f1.x; acc[3] += v * f1.y;
            acc[4] += v * f2.x; acc[5] += v * f2.y;
            acc[6] += v * f3.x; acc[7] += v * f3.y;
        }
    }

    // combine halves + ReLU; lane l16 now holds h1 cols [8*l16, 8*l16+8)
    float h[8];
#pragma unroll
    for (int i = 0; i < 8; i++) {
        float s = acc[i] + __shfl_xor_sync(0xffffffffu, acc[i], 16);
        h[i] = fmaxf(s, 0.f);
    }

    // mat-vec: lane = output col (32 cols); h[k] lives on lane (k>>3)
    float o = b2s[lane];
#pragma unroll
    for (int k = 0; k < HID; k++) {
        float hk = __shfl_sync(0xffffffffu, h[k & 7], k >> 3);
        o += hk * W2s[k * OUT_DIM + lane];
    }
    g_h2h[(size_t)r * OUT_DIM + lane] = __float2half_rn(o);
}

// ---------------------------------------------------------------------------
// SpMM2: 16 lanes per row (half2 each), 2 edges per warp-step, convergent tail.
// ---------------------------------------------------------------------------
__global__ __launch_bounds__(256) void spmm2_csr_kernel(float* __restrict__ out) {
    const int wid  = threadIdx.x >> 5;
    const int lane = threadIdx.x & 31;
    const int half = lane >> 4;
    const int l16  = lane & 15;
    const int r = blockIdx.x * 8 + wid;
    if (r >= N_NODES) return;

    const int s0 = g_rowptr[r];
    const int s1 = g_rowptr[r + 1];

    float2 acc = make_float2(0.f, 0.f);
    for (int base = s0; base < s1; base += 32) {
        int cnt = min(32, s1 - base);
        int2 pk = make_int2(0, 0);
        if (lane < cnt) pk = g_cedge[base + lane];

        int j = 0;
        for (; j + 8 <= cnt; j += 8) {
#pragma unroll
            for (int u = 0; u < 4; u++) {
                int e = j + 2 * u + half;
                int c = __shfl_sync(0xffffffffu, pk.x, e);
                float v = __int_as_float(__shfl_sync(0xffffffffu, pk.y, e));
                __half2 hv = ((const __half2*)(g_h2h + (size_t)c * OUT_DIM))[l16];
                float2 f = __half22float2(hv);
                acc.x += v * f.x;
                acc.y += v * f.y;
            }
        }
        for (; j < cnt; j += 2) {
            int e = j + half;
            int esafe = (e < cnt) ? e : (cnt - 1);
            int c = __shfl_sync(0xffffffffu, pk.x, esafe);
            float v = __int_as_float(__shfl_sync(0xffffffffu, pk.y, esafe));
            if (e >= cnt) v = 0.f;
            __half2 hv = ((const __half2*)(g_h2h + (size_t)c * OUT_DIM))[l16];
            float2 f = __half22float2(hv);
            acc.x += v * f.x;
            acc.y += v * f.y;
        }
    }

    acc.x += __shfl_xor_sync(0xffffffffu, acc.x, 16);
    acc.y += __shfl_xor_sync(0xffffffffu, acc.y, 16);
    if (half == 0)
        *(float2*)(out + (size_t)r * OUT_DIM + 2 * l16) = acc;
}

// ---------------------------------------------------------------------------
// Launch: fork CSR build onto a side stream, overlap with GEMM1.
// ---------------------------------------------------------------------------
extern "C" void kernel_launch(void* const* d_in, const int* in_sizes, int n_in,
                              void* d_out, int out_size) {
    const float* x    = (const float*)d_in[0];
    const int*   erow = (const int*)d_in[1];
    const int*   ecol = (const int*)d_in[2];
    const float* eval = (const float*)d_in[3];
    const float* W1   = (const float*)d_in[4];
    const float* b1   = (const float*)d_in[5];
    const float* W2   = (const float*)d_in[6];
    const float* b2   = (const float*)d_in[7];
    float* out = (float*)d_out;
    const int E = in_sizes[1];

    static cudaStream_t s1 = nullptr;
    static cudaEvent_t ev_fork = nullptr, ev_join = nullptr;
    if (s1 == nullptr) {
        cudaStreamCreateWithFlags(&s1, cudaStreamNonBlocking);
        cudaEventCreateWithFlags(&ev_fork, cudaEventDisableTiming);
        cudaEventCreateWithFlags(&ev_join, cudaEventDisableTiming);
    }

    const int nb_nodes = (N_NODES + 255) / 256;
    const int nb_edges = (E + 255) / 256;
    const int nb_scan  = (N_NODES + 1023) / 1024;
    const int nb_rows8 = (N_NODES + 7) / 8;

    // fork side stream off the capture stream
    cudaEventRecord(ev_fork, 0);
    cudaStreamWaitEvent(s1, ev_fork, 0);

    // CSR build on s1
    zero_cnt_kernel<<<nb_nodes, 256, 0, s1>>>();
    csr_count_kernel<<<nb_edges, 256, 0, s1>>>(erow, E);
    scan1_kernel<<<nb_scan, 1024, 0, s1>>>();
    scan2_kernel<<<1, 128, 0, s1>>>(nb_scan, E);
    scan3_kernel<<<nb_nodes, 256, 0, s1>>>();
    csr_scatter_kernel<<<nb_edges, 256, 0, s1>>>(erow, ecol, eval, E);
    cudaEventRecord(ev_join, s1);

    // GEMM1 on main stream, concurrent with CSR build
    gemm1_mma_kernel<<<(N_NODES + 127) / 128, 256>>>(x, W1, b1);

    // join
    cudaStreamWaitEvent(0, ev_join, 0);

    // fused SpMM1 + ReLU + GEMM2, then SpMM2
    spmm1_fused_kernel<<<nb_rows8, 256>>>(W2, b2);
    spmm2_csr_kernel<<<nb_rows8, 256>>>(out);
}

// round 6
// speedup vs baseline: 3.0022x; 1.0047x over previous
#include <cuda_runtime.h>
#include <cuda_fp16.h>
#include <cuda_bf16.h>

#define N_NODES 100000
#define IN_DIM  256
#define HID     128
#define OUT_DIM 32
#define E_MAX   1600000

// ---------------- device scratch ----------------
__device__ __half g_h0h[(size_t)N_NODES * HID];       // fp16 x@W1+b1
__device__ __half g_h2h[(size_t)N_NODES * OUT_DIM];   // fp16 relu(A@h0)@W2+b2
__device__ int   g_cnt[N_NODES];
__device__ int   g_rowptr[N_NODES + 1];
__device__ int   g_cur[N_NODES];
__device__ int   g_bsum[128];
__device__ int   g_bsumx[128];
__device__ int2  g_cedge[E_MAX];                      // packed {col, val_bits}

// ---------------------------------------------------------------------------
// tf32 helpers
// ---------------------------------------------------------------------------
__device__ __forceinline__ unsigned f2tf32(float f) {
    unsigned u;
    asm("cvt.rna.tf32.f32 %0, %1;" : "=r"(u) : "f"(f));
    return u;
}

__device__ __forceinline__ void mma_tf32(float* d, const unsigned* a, const unsigned* b) {
    asm volatile(
        "mma.sync.aligned.m16n8k8.row.col.f32.tf32.tf32.f32 "
        "{%0,%1,%2,%3}, {%4,%5,%6,%7}, {%8,%9}, {%0,%1,%2,%3};\n"
        : "+f"(d[0]), "+f"(d[1]), "+f"(d[2]), "+f"(d[3])
        : "r"(a[0]), "r"(a[1]), "r"(a[2]), "r"(a[3]), "r"(b[0]), "r"(b[1]));
}

// ---------------------------------------------------------------------------
// GEMM1 (tf32 tensor cores): g_h0h = half(x @ W1 + b1)
// ---------------------------------------------------------------------------
#define BK 32
__global__ __launch_bounds__(256) void gemm1_mma_kernel(const float* __restrict__ X,
                                                        const float* __restrict__ W,
                                                        const float* __restrict__ bias) {
    __shared__ unsigned As[128][BK + 4];
    __shared__ unsigned Bs[BK][HID + 8];

    const int tid  = threadIdx.x;
    const int wid  = tid >> 5;
    const int lane = tid & 31;
    const int g    = lane >> 2;
    const int t    = lane & 3;
    const int wm   = wid >> 2;
    const int wn   = wid & 3;
    const int block_m = blockIdx.x * 128;

    float acc[4][4][4];
#pragma unroll
    for (int mi = 0; mi < 4; mi++)
#pragma unroll
        for (int ni = 0; ni < 4; ni++)
#pragma unroll
            for (int q = 0; q < 4; q++) acc[mi][ni][q] = 0.0f;

    const int ar = tid >> 3;
    const int ac4 = (tid & 7) * 4;
    const int bk = tid >> 5;
    const int bn4 = (tid & 31) * 4;

    for (int k0 = 0; k0 < IN_DIM; k0 += BK) {
#pragma unroll
        for (int i = 0; i < 4; i++) {
            int r = ar + 32 * i;
            int m = block_m + r;
            float4 v = make_float4(0.f, 0.f, 0.f, 0.f);
            if (m < N_NODES) v = *(const float4*)(X + (size_t)m * IN_DIM + k0 + ac4);
            As[r][ac4 + 0] = f2tf32(v.x);
            As[r][ac4 + 1] = f2tf32(v.y);
            As[r][ac4 + 2] = f2tf32(v.z);
            As[r][ac4 + 3] = f2tf32(v.w);
        }
#pragma unroll
        for (int i = 0; i < 4; i++) {
            int k = bk + 8 * i;
            float4 v = *(const float4*)(W + (size_t)(k0 + k) * HID + bn4);
            Bs[k][bn4 + 0] = f2tf32(v.x);
            Bs[k][bn4 + 1] = f2tf32(v.y);
            Bs[k][bn4 + 2] = f2tf32(v.z);
            Bs[k][bn4 + 3] = f2tf32(v.w);
        }
        __syncthreads();

#pragma unroll
        for (int kk = 0; kk < BK; kk += 8) {
            unsigned af[4][4];
            unsigned bf[4][2];
#pragma unroll
            for (int mi = 0; mi < 4; mi++) {
                int m = wm * 64 + mi * 16 + g;
                af[mi][0] = As[m][kk + t];
                af[mi][1] = As[m + 8][kk + t];
                af[mi][2] = As[m][kk + t + 4];
                af[mi][3] = As[m + 8][kk + t + 4];
            }
#pragma unroll
            for (int ni = 0; ni < 4; ni++) {
                int n = wn * 32 + ni * 8 + g;
                bf[ni][0] = Bs[kk + t][n];
                bf[ni][1] = Bs[kk + t + 4][n];
            }
#pragma unroll
            for (int mi = 0; mi < 4; mi++)
#pragma unroll
                for (int ni = 0; ni < 4; ni++)
                    mma_tf32(acc[mi][ni], af[mi], bf[ni]);
        }
        __syncthreads();
    }

#pragma unroll
    for (int ni = 0; ni < 4; ni++) {
        int n = wn * 32 + ni * 8 + 2 * t;
        float b0 = bias[n], b1 = bias[n + 1];
#pragma unroll
        for (int mi = 0; mi < 4; mi++) {
            int r0 = block_m + wm * 64 + mi * 16 + g;
            int r1 = r0 + 8;
            if (r0 < N_NODES)
                *(__half2*)(g_h0h + (size_t)r0 * HID + n) =
                    __floats2half2_rn(acc[mi][ni][0] + b0, acc[mi][ni][1] + b1);
            if (r1 < N_NODES)
                *(__half2*)(g_h0h + (size_t)r1 * HID + n) =
                    __floats2half2_rn(acc[mi][ni][2] + b0, acc[mi][ni][3] + b1);
        }
    }
}

// ---------------------------------------------------------------------------
// CSR build
// ---------------------------------------------------------------------------
__global__ void zero_cnt_kernel() {
    int i = blockIdx.x * 256 + threadIdx.x;
    if (i < N_NODES) g_cnt[i] = 0;
}

__global__ void csr_count_kernel(const int* __restrict__ erow, int E) {
    int e = blockIdx.x * 256 + threadIdx.x;
    if (e < E) atomicAdd(&g_cnt[erow[e]], 1);
}

__global__ __launch_bounds__(1024) void scan1_kernel() {
    __shared__ int s[1024];
    int t = threadIdx.x;
    int i = blockIdx.x * 1024 + t;
    int v = (i < N_NODES) ? g_cnt[i] : 0;
    s[t] = v;
    for (int off = 1; off < 1024; off <<= 1) {
        __syncthreads();
        int tmp = (t >= off) ? s[t - off] : 0;
        __syncthreads();
        s[t] += tmp;
    }
    if (i < N_NODES) g_rowptr[i] = s[t] - v;
    if (t == 1023) g_bsum[blockIdx.x] = s[1023];
}

__global__ void scan2_kernel(int nb, int E) {
    __shared__ int s[128];
    int t = threadIdx.x;
    int v = (t < nb) ? g_bsum[t] : 0;
    s[t] = v;
    for (int off = 1; off < 128; off <<= 1) {
        __syncthreads();
        int tmp = (t >= off) ? s[t - off] : 0;
        __syncthreads();
        s[t] += tmp;
    }
    if (t < nb) g_bsumx[t] = s[t] - v;
    if (t == 0) g_rowptr[N_NODES] = E;
}

__global__ void scan3_kernel() {
    int i = blockIdx.x * 256 + threadIdx.x;
    if (i < N_NODES) {
        int v = g_rowptr[i] + g_bsumx[i >> 10];
        g_rowptr[i] = v;
        g_cur[i] = v;
    }
}

__global__ void csr_scatter_kernel(const int* __restrict__ erow,
                                   const int* __restrict__ ecol,
                                   const float* __restrict__ eval, int E) {
    int e = blockIdx.x * 256 + threadIdx.x;
    if (e < E) {
        int r = erow[e];
        int idx = atomicAdd(&g_cur[r], 1);
        g_cedge[idx] = make_int2(ecol[e], __float_as_int(eval[e]));
    }
}

// ---------------------------------------------------------------------------
// Fused SpMM1 + ReLU + GEMM2.  One warp per row; ALL 32 lanes cooperate on
// each edge (uint2 = 4 halves per lane), 8 edges unrolled -> MLP 8.
// Edge index is warp-uniform so every path is convergent by construction.
// Lane owns h1 cols [4*lane, 4*lane+4).
// ---------------------------------------------------------------------------
__global__ __launch_bounds__(256) void spmm1_fused_kernel(const float* __restrict__ W2,
                                                          const float* __restrict__ b2) {
    __shared__ float W2s[HID * OUT_DIM];   // [k][n]
    __shared__ float b2s[OUT_DIM];
    for (int i = threadIdx.x; i < HID * OUT_DIM; i += 256) W2s[i] = W2[i];
    if (threadIdx.x < OUT_DIM) b2s[threadIdx.x] = b2[threadIdx.x];
    __syncthreads();

    const int wid  = threadIdx.x >> 5;
    const int lane = threadIdx.x & 31;
    const int r = blockIdx.x * 8 + wid;
    if (r >= N_NODES) return;

    const int s0 = g_rowptr[r];
    const int s1 = g_rowptr[r + 1];

    float acc[4];
#pragma unroll
    for (int i = 0; i < 4; i++) acc[i] = 0.f;

    for (int base = s0; base < s1; base += 32) {
        int cnt = min(32, s1 - base);
        int2 pk = make_int2(0, 0);
        if (lane < cnt) pk = g_cedge[base + lane];

        int j = 0;
        for (; j + 8 <= cnt; j += 8) {
            int   c[8];
            float v[8];
#pragma unroll
            for (int u = 0; u < 8; u++) {
                c[u] = __shfl_sync(0xffffffffu, pk.x, j + u);
                v[u] = __int_as_float(__shfl_sync(0xffffffffu, pk.y, j + u));
            }
            uint2 hw[8];
#pragma unroll
            for (int u = 0; u < 8; u++)
                hw[u] = ((const uint2*)(g_h0h + (size_t)c[u] * HID))[lane];
#pragma unroll
            for (int u = 0; u < 8; u++) {
                float2 f0 = __half22float2(*(__half2*)&hw[u].x);
                float2 f1 = __half22float2(*(__half2*)&hw[u].y);
                acc[0] += v[u] * f0.x; acc[1] += v[u] * f0.y;
                acc[2] += v[u] * f1.x; acc[3] += v[u] * f1.y;
            }
        }
        for (; j + 4 <= cnt; j += 4) {
            int   c[4];
            float v[4];
#pragma unroll
            for (int u = 0; u < 4; u++) {
                c[u] = __shfl_sync(0xffffffffu, pk.x, j + u);
                v[u] = __int_as_float(__shfl_sync(0xffffffffu, pk.y, j + u));
            }
            uint2 hw[4];
#pragma unroll
            for (int u = 0; u < 4; u++)
                hw[u] = ((const uint2*)(g_h0h + (size_t)c[u] * HID))[lane];
#pragma unroll
            for (int u = 0; u < 4; u++) {
                float2 f0 = __half22float2(*(__half2*)&hw[u].x);
                float2 f1 = __half22float2(*(__half2*)&hw[u].y);
                acc[0] += v[u] * f0.x; acc[1] += v[u] * f0.y;
                acc[2] += v[u] * f1.x; acc[3] += v[u] * f1.y;
            }
        }
        for (; j < cnt; j++) {
            int c = __shfl_sync(0xffffffffu, pk.x, j);
            float v = __int_as_float(__shfl_sync(0xffffffffu, pk.y, j));
            uint2 hw = ((const uint2*)(g_h0h + (size_t)c * HID))[lane];
            float2 f0 = __half22float2(*(__half2*)&hw.x);
            float2 f1 = __half22float2(*(__half2*)&hw.y);
            acc[0] += v * f0.x; acc[1] += v * f0.y;
            acc[2] += v * f1.x; acc[3] += v * f1.y;
        }
    }

    // ReLU; lane owns h1 cols [4*lane, 4*lane+4)
    float h[4];
#pragma unroll
    for (int i = 0; i < 4; i++) h[i] = fmaxf(acc[i], 0.f);

    // mat-vec: lane = output col (32 cols); h1[k] lives on lane (k>>2), slot (k&3)
    float o = b2s[lane];
#pragma unroll
    for (int k = 0; k < HID; k++) {
        float hk = __shfl_sync(0xffffffffu, h[k & 3], k >> 2);
        o += hk * W2s[k * OUT_DIM + lane];
    }
    g_h2h[(size_t)r * OUT_DIM + lane] = __float2half_rn(o);
}

// ---------------------------------------------------------------------------
// SpMM2: 16 lanes per row (half2 each); two halves process alternating edges,
// 8 edges unrolled per half (16 edges per warp-step) -> MLP 8.
// ---------------------------------------------------------------------------
__global__ __launch_bounds__(256) void spmm2_csr_kernel(float* __restrict__ out) {
    const int wid  = threadIdx.x >> 5;
    const int lane = threadIdx.x & 31;
    const int half = lane >> 4;
    const int l16  = lane & 15;
    const int r = blockIdx.x * 8 + wid;
    if (r >= N_NODES) return;

    const int s0 = g_rowptr[r];
    const int s1 = g_rowptr[r + 1];

    float2 acc = make_float2(0.f, 0.f);
    for (int base = s0; base < s1; base += 32) {
        int cnt = min(32, s1 - base);
        int2 pk = make_int2(0, 0);
        if (lane < cnt) pk = g_cedge[base + lane];

        int j = 0;
        for (; j + 16 <= cnt; j += 16) {
            int   c[8];
            float v[8];
#pragma unroll
            for (int u = 0; u < 8; u++) {
                int e = j + 2 * u + half;
                c[u] = __shfl_sync(0xffffffffu, pk.x, e);
                v[u] = __int_as_float(__shfl_sync(0xffffffffu, pk.y, e));
            }
            __half2 hv[8];
#pragma unroll
            for (int u = 0; u < 8; u++)
                hv[u] = ((const __half2*)(g_h2h + (size_t)c[u] * OUT_DIM))[l16];
#pragma unroll
            for (int u = 0; u < 8; u++) {
                float2 f = __half22float2(hv[u]);
                acc.x += v[u] * f.x;
                acc.y += v[u] * f.y;
            }
        }
        for (; j < cnt; j += 2) {
            int e = j + half;
            int esafe = (e < cnt) ? e : (cnt - 1);
            int c = __shfl_sync(0xffffffffu, pk.x, esafe);
            float v = __int_as_float(__shfl_sync(0xffffffffu, pk.y, esafe));
            if (e >= cnt) v = 0.f;
            __half2 hv = ((const __half2*)(g_h2h + (size_t)c * OUT_DIM))[l16];
            float2 f = __half22float2(hv);
            acc.x += v * f.x;
            acc.y += v * f.y;
        }
    }

    acc.x += __shfl_xor_sync(0xffffffffu, acc.x, 16);
    acc.y += __shfl_xor_sync(0xffffffffu, acc.y, 16);
    if (half == 0)
        *(float2*)(out + (size_t)r * OUT_DIM + 2 * l16) = acc;
}

// ---------------------------------------------------------------------------
// Launch: fork CSR build onto a side stream, overlap with GEMM1.
// ---------------------------------------------------------------------------
extern "C" void kernel_launch(void* const* d_in, const int* in_sizes, int n_in,
                              void* d_out, int out_size) {
    const float* x    = (const float*)d_in[0];
    const int*   erow = (const int*)d_in[1];
    const int*   ecol = (const int*)d_in[2];
    const float* eval = (const float*)d_in[3];
    const float* W1   = (const float*)d_in[4];
    const float* b1   = (const float*)d_in[5];
    const float* W2   = (const float*)d_in[6];
    const float* b2   = (const float*)d_in[7];
    float* out = (float*)d_out;
    const int E = in_sizes[1];

    static cudaStream_t s1 = nullptr;
    static cudaEvent_t ev_fork = nullptr, ev_join = nullptr;
    if (s1 == nullptr) {
        cudaStreamCreateWithFlags(&s1, cudaStreamNonBlocking);
        cudaEventCreateWithFlags(&ev_fork, cudaEventDisableTiming);
        cudaEventCreateWithFlags(&ev_join, cudaEventDisableTiming);
    }

    const int nb_nodes = (N_NODES + 255) / 256;
    const int nb_edges = (E + 255) / 256;
    const int nb_scan  = (N_NODES + 1023) / 1024;
    const int nb_rows8 = (N_NODES + 7) / 8;

    // fork side stream off the capture stream
    cudaEventRecord(ev_fork, 0);
    cudaStreamWaitEvent(s1, ev_fork, 0);

    // CSR build on s1
    zero_cnt_kernel<<<nb_nodes, 256, 0, s1>>>();
    csr_count_kernel<<<nb_edges, 256, 0, s1>>>(erow, E);
    scan1_kernel<<<nb_scan, 1024, 0, s1>>>();
    scan2_kernel<<<1, 128, 0, s1>>>(nb_scan, E);
    scan3_kernel<<<nb_nodes, 256, 0, s1>>>();
    csr_scatter_kernel<<<nb_edges, 256, 0, s1>>>(erow, ecol, eval, E);
    cudaEventRecord(ev_join, s1);

    // GEMM1 on main stream, concurrent with CSR build
    gemm1_mma_kernel<<<(N_NODES + 127) / 128, 256>>>(x, W1, b1);

    // join
    cudaStreamWaitEvent(0, ev_join, 0);

    // fused SpMM1 + ReLU + GEMM2, then SpMM2
    spmm1_fused_kernel<<<nb_rows8, 256>>>(W2, b2);
    spmm2_csr_kernel<<<nb_rows8, 256>>>(out);
}

// round 8
// speedup vs baseline: 3.0427x; 1.0135x over previous
#include <cuda_runtime.h>
#include <cuda_fp16.h>
#include <cuda_bf16.h>

#define N_NODES 100000
#define IN_DIM  256
#define HID     128
#define OUT_DIM 32
#define E_MAX   1600000

// ---------------- device scratch ----------------
__device__ __half g_h0h[(size_t)N_NODES * HID];       // fp16 x@W1+b1
__device__ __half g_h2h[(size_t)N_NODES * OUT_DIM];   // fp16 relu(A@h0)@W2+b2
__device__ int   g_cnt[N_NODES];
__device__ int   g_rowptr[N_NODES + 1];
__device__ int   g_cur[N_NODES];
__device__ int   g_bsum[128];
__device__ int   g_bsumx[128];
__device__ int2  g_cedge[E_MAX];                      // packed {col, val_bits}

// ---------------------------------------------------------------------------
// helpers
// ---------------------------------------------------------------------------
__device__ __forceinline__ unsigned f2tf32(float f) {
    unsigned u;
    asm("cvt.rna.tf32.f32 %0, %1;" : "=r"(u) : "f"(f));
    return u;
}

__device__ __forceinline__ void mma_tf32(float* d, const unsigned* a, const unsigned* b) {
    asm volatile(
        "mma.sync.aligned.m16n8k8.row.col.f32.tf32.tf32.f32 "
        "{%0,%1,%2,%3}, {%4,%5,%6,%7}, {%8,%9}, {%0,%1,%2,%3};\n"
        : "+f"(d[0]), "+f"(d[1]), "+f"(d[2]), "+f"(d[3])
        : "r"(a[0]), "r"(a[1]), "r"(a[2]), "r"(a[3]), "r"(b[0]), "r"(b[1]));
}

__device__ __forceinline__ void cp_async16(void* smem_dst, const void* gsrc, int src_bytes) {
    unsigned saddr = (unsigned)__cvta_generic_to_shared(smem_dst);
    asm volatile("cp.async.cg.shared.global [%0], [%1], 16, %2;\n"
                 :: "r"(saddr), "l"(gsrc), "r"(src_bytes));
}
__device__ __forceinline__ void cp_async_commit() {
    asm volatile("cp.async.commit_group;\n");
}
__device__ __forceinline__ void cp_async_wait1() {
    asm volatile("cp.async.wait_group 1;\n");
}
__device__ __forceinline__ void cp_async_wait0() {
    asm volatile("cp.async.wait_group 0;\n");
}

// ---------------------------------------------------------------------------
// GEMM1 (tf32 mma, cp.async double-buffered): g_h0h = half(x @ W1 + b1)
// 128x128 block tile, BK2=16, 2 stages, 256 threads (8 warps 2x4, 64x32/warp)
// ---------------------------------------------------------------------------
#define BK2 16
#define NITER (IN_DIM / BK2)
__global__ __launch_bounds__(256) void gemm1_mma_kernel(const float* __restrict__ X,
                                                        const float* __restrict__ W,
                                                        const float* __restrict__ bias) {
    __shared__ float As[2][128][BK2 + 4];   // 2 x 10.24 KB
    __shared__ float Bs[2][BK2][HID + 8];   // 2 x  8.70 KB

    const int tid  = threadIdx.x;
    const int wid  = tid >> 5;
    const int lane = tid & 31;
    const int g    = lane >> 2;
    const int t    = lane & 3;
    const int wm   = wid >> 2;
    const int wn   = wid & 3;
    const int block_m = blockIdx.x * 128;

    float acc[4][4][4];
#pragma unroll
    for (int mi = 0; mi < 4; mi++)
#pragma unroll
        for (int ni = 0; ni < 4; ni++)
#pragma unroll
            for (int q = 0; q < 4; q++) acc[mi][ni][q] = 0.0f;

    // A: 128 rows x 16 floats = 512 chunks(16B); thread does chunks tid, tid+256
    const int ac0_row = tid >> 2;              // 0..63
    const int ac0_col = (tid & 3) * 4;
    const int ac1_row = (tid + 256) >> 2;      // 64..127
    const int ac1_col = ((tid + 256) & 3) * 4;
    // B: 16 rows x 128 floats = 512 chunks(16B); thread does chunks tid, tid+256
    const int bc0_row = tid >> 5;              // 0..7
    const int bc0_col = (tid & 31) * 4;
    const int bc1_row = (tid + 256) >> 5;      // 8..15
    const int bc1_col = ((tid + 256) & 31) * 4;

    auto load_stage = [&](int s, int k0) {
        {
            int m = block_m + ac0_row;
            const float* src = X + (size_t)(m < N_NODES ? m : 0) * IN_DIM + k0 + ac0_col;
            cp_async16(&As[s][ac0_row][ac0_col], src, (m < N_NODES) ? 16 : 0);
        }
        {
            int m = block_m + ac1_row;
            const float* src = X + (size_t)(m < N_NODES ? m : 0) * IN_DIM + k0 + ac1_col;
            cp_async16(&As[s][ac1_row][ac1_col], src, (m < N_NODES) ? 16 : 0);
        }
        cp_async16(&Bs[s][bc0_row][bc0_col],
                   W + (size_t)(k0 + bc0_row) * HID + bc0_col, 16);
        cp_async16(&Bs[s][bc1_row][bc1_col],
                   W + (size_t)(k0 + bc1_row) * HID + bc1_col, 16);
    };

    load_stage(0, 0);
    cp_async_commit();

    for (int it = 0; it < NITER; it++) {
        const int s = it & 1;
        if (it + 1 < NITER) {
            load_stage((it + 1) & 1, (it + 1) * BK2);
            cp_async_commit();
            cp_async_wait1();
        } else {
            cp_async_wait0();
        }
        __syncthreads();

#pragma unroll
        for (int kk = 0; kk < BK2; kk += 8) {
            unsigned af[4][4];
            unsigned bf[4][2];
#pragma unroll
            for (int mi = 0; mi < 4; mi++) {
                int m = wm * 64 + mi * 16 + g;
                af[mi][0] = f2tf32(As[s][m][kk + t]);
                af[mi][1] = f2tf32(As[s][m + 8][kk + t]);
                af[mi][2] = f2tf32(As[s][m][kk + t + 4]);
                af[mi][3] = f2tf32(As[s][m + 8][kk + t + 4]);
            }
#pragma unroll
            for (int ni = 0; ni < 4; ni++) {
                int n = wn * 32 + ni * 8 + g;
                bf[ni][0] = f2tf32(Bs[s][kk + t][n]);
                bf[ni][1] = f2tf32(Bs[s][kk + t + 4][n]);
            }
#pragma unroll
            for (int mi = 0; mi < 4; mi++)
#pragma unroll
                for (int ni = 0; ni < 4; ni++)
                    mma_tf32(acc[mi][ni], af[mi], bf[ni]);
        }
        __syncthreads();
    }

#pragma unroll
    for (int ni = 0; ni < 4; ni++) {
        int n = wn * 32 + ni * 8 + 2 * t;
        float b0 = bias[n], b1 = bias[n + 1];
#pragma unroll
        for (int mi = 0; mi < 4; mi++) {
            int r0 = block_m + wm * 64 + mi * 16 + g;
            int r1 = r0 + 8;
            if (r0 < N_NODES)
                *(__half2*)(g_h0h + (size_t)r0 * HID + n) =
                    __floats2half2_rn(acc[mi][ni][0] + b0, acc[mi][ni][1] + b1);
            if (r1 < N_NODES)
                *(__half2*)(g_h0h + (size_t)r1 * HID + n) =
                    __floats2half2_rn(acc[mi][ni][2] + b0, acc[mi][ni][3] + b1);
        }
    }
}

// ---------------------------------------------------------------------------
// CSR build
// ---------------------------------------------------------------------------
__global__ void zero_cnt_kernel() {
    int i = blockIdx.x * 256 + threadIdx.x;
    if (i < N_NODES) g_cnt[i] = 0;
}

__global__ void csr_count_kernel(const int* __restrict__ erow, int E) {
    int e = blockIdx.x * 256 + threadIdx.x;
    if (e < E) atomicAdd(&g_cnt[erow[e]], 1);
}

__global__ __launch_bounds__(1024) void scan1_kernel() {
    __shared__ int s[1024];
    int t = threadIdx.x;
    int i = blockIdx.x * 1024 + t;
    int v = (i < N_NODES) ? g_cnt[i] : 0;
    s[t] = v;
    for (int off = 1; off < 1024; off <<= 1) {
        __syncthreads();
        int tmp = (t >= off) ? s[t - off] : 0;
        __syncthreads();
        s[t] += tmp;
    }
    if (i < N_NODES) g_rowptr[i] = s[t] - v;
    if (t == 1023) g_bsum[blockIdx.x] = s[1023];
}

__global__ void scan2_kernel(int nb, int E) {
    __shared__ int s[128];
    int t = threadIdx.x;
    int v = (t < nb) ? g_bsum[t] : 0;
    s[t] = v;
    for (int off = 1; off < 128; off <<= 1) {
        __syncthreads();
        int tmp = (t >= off) ? s[t - off] : 0;
        __syncthreads();
        s[t] += tmp;
    }
    if (t < nb) g_bsumx[t] = s[t] - v;
    if (t == 0) g_rowptr[N_NODES] = E;
}

__global__ void scan3_kernel() {
    int i = blockIdx.x * 256 + threadIdx.x;
    if (i < N_NODES) {
        int v = g_rowptr[i] + g_bsumx[i >> 10];
        g_rowptr[i] = v;
        g_cur[i] = v;
    }
}

__global__ void csr_scatter_kernel(const int* __restrict__ erow,
                                   const int* __restrict__ ecol,
                                   const float* __restrict__ eval, int E) {
    int e = blockIdx.x * 256 + threadIdx.x;
    if (e < E) {
        int r = erow[e];
        int idx = atomicAdd(&g_cur[r], 1);
        g_cedge[idx] = make_int2(ecol[e], __float_as_int(eval[e]));
    }
}

// ---------------------------------------------------------------------------
// Fused SpMM1 + ReLU + GEMM2.  One warp per row; 32 lanes per edge
// (uint2 = 4 halves each), 8 edges unrolled -> MLP 8.  Warp-uniform edge
// index => convergent everywhere.  Lane owns h1 cols [4*lane, 4*lane+4).
// ---------------------------------------------------------------------------
__global__ __launch_bounds__(256) void spmm1_fused_kernel(const float* __restrict__ W2,
                                                          const float* __restrict__ b2) {
    __shared__ float W2s[HID * OUT_DIM];   // [k][n]
    __shared__ float b2s[OUT_DIM];
    for (int i = threadIdx.x; i < HID * OUT_DIM; i += 256) W2s[i] = W2[i];
    if (threadIdx.x < OUT_DIM) b2s[threadIdx.x] = b2[threadIdx.x];
    __syncthreads();

    const int wid  = threadIdx.x >> 5;
    const int lane = threadIdx.x & 31;
    const int r = blockIdx.x * 8 + wid;
    if (r >= N_NODES) return;

    const int s0 = g_rowptr[r];
    const int s1 = g_rowptr[r + 1];

    float acc[4];
#pragma unroll
    for (int i = 0; i < 4; i++) acc[i] = 0.f;

    for (int base = s0; base < s1; base += 32) {
        int cnt = min(32, s1 - base);
        int2 pk = make_int2(0, 0);
        if (lane < cnt) pk = g_cedge[base + lane];

        int j = 0;
        for (; j + 8 <= cnt; j += 8) {
            int   c[8];
            float v[8];
#pragma unroll
            for (int u = 0; u < 8; u++) {
                c[u] = __shfl_sync(0xffffffffu, pk.x, j + u);
                v[u] = __int_as_float(__shfl_sync(0xffffffffu, pk.y, j + u));
            }
            uint2 hw[8];
#pragma unroll
            for (int u = 0; u < 8; u++)
                hw[u] = ((const uint2*)(g_h0h + (size_t)c[u] * HID))[lane];
#pragma unroll
            for (int u = 0; u < 8; u++) {
                float2 f0 = __half22float2(*(__half2*)&hw[u].x);
                float2 f1 = __half22float2(*(__half2*)&hw[u].y);
                acc[0] += v[u] * f0.x; acc[1] += v[u] * f0.y;
                acc[2] += v[u] * f1.x; acc[3] += v[u] * f1.y;
            }
        }
        for (; j + 4 <= cnt; j += 4) {
            int   c[4];
            float v[4];
#pragma unroll
            for (int u = 0; u < 4; u++) {
                c[u] = __shfl_sync(0xffffffffu, pk.x, j + u);
                v[u] = __int_as_float(__shfl_sync(0xffffffffu, pk.y, j + u));
            }
            uint2 hw[4];
#pragma unroll
            for (int u = 0; u < 4; u++)
                hw[u] = ((const uint2*)(g_h0h + (size_t)c[u] * HID))[lane];
#pragma unroll
            for (int u = 0; u < 4; u++) {
                float2 f0 = __half22float2(*(__half2*)&hw[u].x);
                float2 f1 = __half22float2(*(__half2*)&hw[u].y);
                acc[0] += v[u] * f0.x; acc[1] += v[u] * f0.y;
                acc[2] += v[u] * f1.x; acc[3] += v[u] * f1.y;
            }
        }
        for (; j < cnt; j++) {
            int c = __shfl_sync(0xffffffffu, pk.x, j);
            float v = __int_as_float(__shfl_sync(0xffffffffu, pk.y, j));
            uint2 hw = ((const uint2*)(g_h0h + (size_t)c * HID))[lane];
            float2 f0 = __half22float2(*(__half2*)&hw.x);
            float2 f1 = __half22float2(*(__half2*)&hw.y);
            acc[0] += v * f0.x; acc[1] += v * f0.y;
            acc[2] += v * f1.x; acc[3] += v * f1.y;
        }
    }

    float h[4];
#pragma unroll
    for (int i = 0; i < 4; i++) h[i] = fmaxf(acc[i], 0.f);

    float o = b2s[lane];
#pragma unroll
    for (int k = 0; k < HID; k++) {
        float hk = __shfl_sync(0xffffffffu, h[k & 3], k >> 2);
        o += hk * W2s[k * OUT_DIM + lane];
    }
    g_h2h[(size_t)r * OUT_DIM + lane] = __float2half_rn(o);
}

// ---------------------------------------------------------------------------
// SpMM2: 16 lanes per row (half2 each); halves process alternating edges,
// 8 edges unrolled per half (16 edges per warp-step) -> MLP 8.
// ---------------------------------------------------------------------------
__global__ __launch_bounds__(256) void spmm2_csr_kernel(float* __restrict__ out) {
    const int wid  = threadIdx.x >> 5;
    const int lane = threadIdx.x & 31;
    const int half = lane >> 4;
    const int l16  = lane & 15;
    const int r = blockIdx.x * 8 + wid;
    if (r >= N_NODES) return;

    const int s0 = g_rowptr[r];
    const int s1 = g_rowptr[r + 1];

    float2 acc = make_float2(0.f, 0.f);
    for (int base = s0; base < s1; base += 32) {
        int cnt = min(32, s1 - base);
        int2 pk = make_int2(0, 0);
        if (lane < cnt) pk = g_cedge[base + lane];

        int j = 0;
        for (; j + 16 <= cnt; j += 16) {
            int   c[8];
            float v[8];
#pragma unroll
            for (int u = 0; u < 8; u++) {
                int e = j + 2 * u + half;
                c[u] = __shfl_sync(0xffffffffu, pk.x, e);
                v[u] = __int_as_float(__shfl_sync(0xffffffffu, pk.y, e));
            }
            __half2 hv[8];
#pragma unroll
            for (int u = 0; u < 8; u++)
                hv[u] = ((const __half2*)(g_h2h + (size_t)c[u] * OUT_DIM))[l16];
#pragma unroll
            for (int u = 0; u < 8; u++) {
                float2 f = __half22float2(hv[u]);
                acc.x += v[u] * f.x;
                acc.y += v[u] * f.y;
            }
        }
        for (; j < cnt; j += 2) {
            int e = j + half;
            int esafe = (e < cnt) ? e : (cnt - 1);
            int c = __shfl_sync(0xffffffffu, pk.x, esafe);
            float v = __int_as_float(__shfl_sync(0xffffffffu, pk.y, esafe));
            if (e >= cnt) v = 0.f;
            __half2 hv = ((const __half2*)(g_h2h + (size_t)c * OUT_DIM))[l16];
            float2 f = __half22float2(hv);
            acc.x += v * f.x;
            acc.y += v * f.y;
        }
    }

    acc.x += __shfl_xor_sync(0xffffffffu, acc.x, 16);
    acc.y += __shfl_xor_sync(0xffffffffu, acc.y, 16);
    if (half == 0)
        *(float2*)(out + (size_t)r * OUT_DIM + 2 * l16) = acc;
}

// ---------------------------------------------------------------------------
// Launch: CSR build on side stream overlapping GEMM1 on main stream.
// Submission order puts gemm1 as the 4th kernel (ncu profiles launch #4).
// ---------------------------------------------------------------------------
extern "C" void kernel_launch(void* const* d_in, const int* in_sizes, int n_in,
                              void* d_out, int out_size) {
    const float* x    = (const float*)d_in[0];
    const int*   erow = (const int*)d_in[1];
    const int*   ecol = (const int*)d_in[2];
    const float* eval = (const float*)d_in[3];
    const float* W1   = (const float*)d_in[4];
    const float* b1   = (const float*)d_in[5];
    const float* W2   = (const float*)d_in[6];
    const float* b2   = (const float*)d_in[7];
    float* out = (float*)d_out;
    const int E = in_sizes[1];

    static cudaStream_t s1 = nullptr;
    static cudaEvent_t ev_fork = nullptr, ev_join = nullptr;
    if (s1 == nullptr) {
        cudaStreamCreateWithFlags(&s1, cudaStreamNonBlocking);
        cudaEventCreateWithFlags(&ev_fork, cudaEventDisableTiming);
        cudaEventCreateWithFlags(&ev_join, cudaEventDisableTiming);
    }

    const int nb_nodes = (N_NODES + 255) / 256;
    const int nb_edges = (E + 255) / 256;
    const int nb_scan  = (N_NODES + 1023) / 1024;
    const int nb_rows8 = (N_NODES + 7) / 8;

    // fork side stream off the capture stream
    cudaEventRecord(ev_fork, 0);
    cudaStreamWaitEvent(s1, ev_fork, 0);

    // CSR build part 1 on s1 (launches 1-3)
    zero_cnt_kernel<<<nb_nodes, 256, 0, s1>>>();
    csr_count_kernel<<<nb_edges, 256, 0, s1>>>(erow, E);
    scan1_kernel<<<nb_scan, 1024, 0, s1>>>();

    // GEMM1 on main stream (launch #4 -> ncu profiles this)
    gemm1_mma_kernel<<<(N_NODES + 127) / 128, 256>>>(x, W1, b1);

    // CSR build part 2 on s1
    scan2_kernel<<<1, 128, 0, s1>>>(nb_scan, E);
    scan3_kernel<<<nb_nodes, 256, 0, s1>>>();
    csr_scatter_kernel<<<nb_edges, 256, 0, s1>>>(erow, ecol, eval, E);
    cudaEventRecord(ev_join, s1);

    // join
    cudaStreamWaitEvent(0, ev_join, 0);

    // fused SpMM1 + ReLU + GEMM2, then SpMM2
    spmm1_fused_kernel<<<nb_rows8, 256>>>(W2, b2);
    spmm2_csr_kernel<<<nb_rows8, 256>>>(out);
}

// round 9
// speedup vs baseline: 4.3229x; 1.4207x over previous
#include <cuda_runtime.h>
#include <cuda_fp16.h>
#include <cuda_bf16.h>

#define N_NODES 100000
#define IN_DIM  256
#define HID     128
#define OUT_DIM 32
#define E_MAX   1600000

// ---------------- device scratch ----------------
__device__ __half g_h0h[(size_t)N_NODES * HID];       // fp16 x@W1+b1
__device__ __half g_h1h[(size_t)N_NODES * HID];       // fp16 relu(A@h0)
__device__ __half g_h2h[(size_t)N_NODES * OUT_DIM];   // fp16 h1@W2+b2
__device__ int   g_cnt[N_NODES];                      // zero at entry (rotated)
__device__ int   g_rowptr[N_NODES + 1];
__device__ int   g_cur[N_NODES];
__device__ int   g_bsum[128];
__device__ int2  g_cedge[E_MAX];                      // packed {col, val_bits}

// ---------------------------------------------------------------------------
// mma helpers
// ---------------------------------------------------------------------------
__device__ __forceinline__ void mma_tf32(float* d, const unsigned* a, const unsigned* b) {
    asm volatile(
        "mma.sync.aligned.m16n8k8.row.col.f32.tf32.tf32.f32 "
        "{%0,%1,%2,%3}, {%4,%5,%6,%7}, {%8,%9}, {%0,%1,%2,%3};\n"
        : "+f"(d[0]), "+f"(d[1]), "+f"(d[2]), "+f"(d[3])
        : "r"(a[0]), "r"(a[1]), "r"(a[2]), "r"(a[3]), "r"(b[0]), "r"(b[1]));
}

__device__ __forceinline__ void mma_f16(float* d, const unsigned* a, const unsigned* b) {
    asm volatile(
        "mma.sync.aligned.m16n8k16.row.col.f32.f16.f16.f32 "
        "{%0,%1,%2,%3}, {%4,%5,%6,%7}, {%8,%9}, {%0,%1,%2,%3};\n"
        : "+f"(d[0]), "+f"(d[1]), "+f"(d[2]), "+f"(d[3])
        : "r"(a[0]), "r"(a[1]), "r"(a[2]), "r"(a[3]), "r"(b[0]), "r"(b[1]));
}

__device__ __forceinline__ void cp_async16(void* smem_dst, const void* gsrc, int src_bytes) {
    unsigned saddr = (unsigned)__cvta_generic_to_shared(smem_dst);
    asm volatile("cp.async.cg.shared.global [%0], [%1], 16, %2;\n"
                 :: "r"(saddr), "l"(gsrc), "r"(src_bytes));
}
__device__ __forceinline__ void cp_async_commit() { asm volatile("cp.async.commit_group;\n"); }
__device__ __forceinline__ void cp_async_wait1()  { asm volatile("cp.async.wait_group 1;\n"); }
__device__ __forceinline__ void cp_async_wait0()  { asm volatile("cp.async.wait_group 0;\n"); }

// ---------------------------------------------------------------------------
// GEMM1 (tf32 mma, cp.async double-buffered): g_h0h = half(x @ W1 + b1)
// Raw fp32 bits fed to tf32 mma (HW truncates mantissa; no cvt instructions).
// ---------------------------------------------------------------------------
#define BK2 16
#define NITER (IN_DIM / BK2)
__global__ __launch_bounds__(256) void gemm1_mma_kernel(const float* __restrict__ X,
                                                        const float* __restrict__ W,
                                                        const float* __restrict__ bias) {
    __shared__ float As[2][128][BK2 + 4];
    __shared__ float Bs[2][BK2][HID + 8];

    const int tid  = threadIdx.x;
    const int wid  = tid >> 5;
    const int lane = tid & 31;
    const int g    = lane >> 2;
    const int t    = lane & 3;
    const int wm   = wid >> 2;
    const int wn   = wid & 3;
    const int block_m = blockIdx.x * 128;

    float acc[4][4][4];
#pragma unroll
    for (int mi = 0; mi < 4; mi++)
#pragma unroll
        for (int ni = 0; ni < 4; ni++)
#pragma unroll
            for (int q = 0; q < 4; q++) acc[mi][ni][q] = 0.0f;

    const int ac0_row = tid >> 2;
    const int ac0_col = (tid & 3) * 4;
    const int ac1_row = (tid + 256) >> 2;
    const int ac1_col = ((tid + 256) & 3) * 4;
    const int bc0_row = tid >> 5;
    const int bc0_col = (tid & 31) * 4;
    const int bc1_row = (tid + 256) >> 5;
    const int bc1_col = ((tid + 256) & 31) * 4;

    auto load_stage = [&](int s, int k0) {
        {
            int m = block_m + ac0_row;
            const float* src = X + (size_t)(m < N_NODES ? m : 0) * IN_DIM + k0 + ac0_col;
            cp_async16(&As[s][ac0_row][ac0_col], src, (m < N_NODES) ? 16 : 0);
        }
        {
            int m = block_m + ac1_row;
            const float* src = X + (size_t)(m < N_NODES ? m : 0) * IN_DIM + k0 + ac1_col;
            cp_async16(&As[s][ac1_row][ac1_col], src, (m < N_NODES) ? 16 : 0);
        }
        cp_async16(&Bs[s][bc0_row][bc0_col],
                   W + (size_t)(k0 + bc0_row) * HID + bc0_col, 16);
        cp_async16(&Bs[s][bc1_row][bc1_col],
                   W + (size_t)(k0 + bc1_row) * HID + bc1_col, 16);
    };

    load_stage(0, 0);
    cp_async_commit();

    for (int it = 0; it < NITER; it++) {
        const int s = it & 1;
        if (it + 1 < NITER) {
            load_stage((it + 1) & 1, (it + 1) * BK2);
            cp_async_commit();
            cp_async_wait1();
        } else {
            cp_async_wait0();
        }
        __syncthreads();

#pragma unroll
        for (int kk = 0; kk < BK2; kk += 8) {
            unsigned af[4][4];
            unsigned bf[4][2];
#pragma unroll
            for (int mi = 0; mi < 4; mi++) {
                int m = wm * 64 + mi * 16 + g;
                af[mi][0] = __float_as_uint(As[s][m][kk + t]);
                af[mi][1] = __float_as_uint(As[s][m + 8][kk + t]);
                af[mi][2] = __float_as_uint(As[s][m][kk + t + 4]);
                af[mi][3] = __float_as_uint(As[s][m + 8][kk + t + 4]);
            }
#pragma unroll
            for (int ni = 0; ni < 4; ni++) {
                int n = wn * 32 + ni * 8 + g;
                bf[ni][0] = __float_as_uint(Bs[s][kk + t][n]);
                bf[ni][1] = __float_as_uint(Bs[s][kk + t + 4][n]);
            }
#pragma unroll
            for (int mi = 0; mi < 4; mi++)
#pragma unroll
                for (int ni = 0; ni < 4; ni++)
                    mma_tf32(acc[mi][ni], af[mi], bf[ni]);
        }
        __syncthreads();
    }

#pragma unroll
    for (int ni = 0; ni < 4; ni++) {
        int n = wn * 32 + ni * 8 + 2 * t;
        float b0 = bias[n], b1 = bias[n + 1];
#pragma unroll
        for (int mi = 0; mi < 4; mi++) {
            int r0 = block_m + wm * 64 + mi * 16 + g;
            int r1 = r0 + 8;
            if (r0 < N_NODES)
                *(__half2*)(g_h0h + (size_t)r0 * HID + n) =
                    __floats2half2_rn(acc[mi][ni][0] + b0, acc[mi][ni][1] + b1);
            if (r1 < N_NODES)
                *(__half2*)(g_h0h + (size_t)r1 * HID + n) =
                    __floats2half2_rn(acc[mi][ni][2] + b0, acc[mi][ni][3] + b1);
        }
    }
}

// ---------------------------------------------------------------------------
// CSR build.  g_cnt is zero on entry (static init on first call; re-zeroed by
// scan23 on every call thereafter -> invariant holds for all graph replays).
// ---------------------------------------------------------------------------
__global__ void csr_count_kernel(const int* __restrict__ erow, int E) {
    int e = blockIdx.x * 256 + threadIdx.x;
    if (e < E) atomicAdd(&g_cnt[erow[e]], 1);
}

__global__ __launch_bounds__(1024) void scan1_kernel() {
    __shared__ int s[1024];
    int t = threadIdx.x;
    int i = blockIdx.x * 1024 + t;
    int v = (i < N_NODES) ? g_cnt[i] : 0;
    s[t] = v;
    for (int off = 1; off < 1024; off <<= 1) {
        __syncthreads();
        int tmp = (t >= off) ? s[t - off] : 0;
        __syncthreads();
        s[t] += tmp;
    }
    if (i < N_NODES) g_rowptr[i] = s[t] - v;
    if (t == 1023) g_bsum[blockIdx.x] = s[1023];
}

// merged scan2+scan3: each block redundantly scans <=128 block sums in smem,
// applies the offset to its node range, initializes g_cur, re-zeroes g_cnt.
__global__ void scan23_kernel(int nb, int E) {
    __shared__ int s[128];
    int t = threadIdx.x;
    int v = (t < 128) ? ((t < nb) ? g_bsum[t] : 0) : 0;
    if (t < 128) s[t] = v;
    __syncthreads();
    for (int off = 1; off < 128; off <<= 1) {
        int tmp = (t < 128 && t >= off) ? s[t - off] : 0;
        __syncthreads();
        if (t < 128) s[t] += tmp;
        __syncthreads();
    }
    int blk = (int)(blockIdx.x >> 2);            // 256-node block -> 1024-chunk id
    int offset = (blk > 0) ? s[blk - 1] : 0;     // exclusive prefix
    int i = blockIdx.x * 256 + t;
    if (i < N_NODES) {
        int val = g_rowptr[i] + offset;
        g_rowptr[i] = val;
        g_cur[i] = val;
        g_cnt[i] = 0;                            // re-zero for next launch
    }
    if (blockIdx.x == 0 && t == 0) g_rowptr[N_NODES] = E;
}

__global__ void csr_scatter_kernel(const int* __restrict__ erow,
                                   const int* __restrict__ ecol,
                                   const float* __restrict__ eval, int E) {
    int e = blockIdx.x * 256 + threadIdx.x;
    if (e < E) {
        int r = erow[e];
        int idx = atomicAdd(&g_cur[r], 1);
        g_cedge[idx] = make_int2(ecol[e], __float_as_int(eval[e]));
    }
}

// ---------------------------------------------------------------------------
// SpMM1 + ReLU: g_h1h[r] = relu(sum_e val * g_h0h[col]).  One warp per row;
// 32 lanes x uint2 (4 halves), 8 edges unrolled -> MLP 8; all convergent.
// ---------------------------------------------------------------------------
__global__ __launch_bounds__(256) void spmm1_kernel() {
    const int wid  = threadIdx.x >> 5;
    const int lane = threadIdx.x & 31;
    const int r = blockIdx.x * 8 + wid;
    if (r >= N_NODES) return;

    const int s0 = g_rowptr[r];
    const int s1 = g_rowptr[r + 1];

    float acc[4];
#pragma unroll
    for (int i = 0; i < 4; i++) acc[i] = 0.f;

    for (int base = s0; base < s1; base += 32) {
        int cnt = min(32, s1 - base);
        int2 pk = make_int2(0, 0);
        if (lane < cnt) pk = g_cedge[base + lane];

        int j = 0;
        for (; j + 8 <= cnt; j += 8) {
            int   c[8];
            float v[8];
#pragma unroll
            for (int u = 0; u < 8; u++) {
                c[u] = __shfl_sync(0xffffffffu, pk.x, j + u);
                v[u] = __int_as_float(__shfl_sync(0xffffffffu, pk.y, j + u));
            }
            uint2 hw[8];
#pragma unroll
            for (int u = 0; u < 8; u++)
                hw[u] = ((const uint2*)(g_h0h + (size_t)c[u] * HID))[lane];
#pragma unroll
            for (int u = 0; u < 8; u++) {
                float2 f0 = __half22float2(*(__half2*)&hw[u].x);
                float2 f1 = __half22float2(*(__half2*)&hw[u].y);
                acc[0] += v[u] * f0.x; acc[1] += v[u] * f0.y;
                acc[2] += v[u] * f1.x; acc[3] += v[u] * f1.y;
            }
        }
        for (; j + 4 <= cnt; j += 4) {
            int   c[4];
            float v[4];
#pragma unroll
            for (int u = 0; u < 4; u++) {
                c[u] = __shfl_sync(0xffffffffu, pk.x, j + u);
                v[u] = __int_as_float(__shfl_sync(0xffffffffu, pk.y, j + u));
            }
            uint2 hw[4];
#pragma unroll
            for (int u = 0; u < 4; u++)
                hw[u] = ((const uint2*)(g_h0h + (size_t)c[u] * HID))[lane];
#pragma unroll
            for (int u = 0; u < 4; u++) {
                float2 f0 = __half22float2(*(__half2*)&hw[u].x);
                float2 f1 = __half22float2(*(__half2*)&hw[u].y);
                acc[0] += v[u] * f0.x; acc[1] += v[u] * f0.y;
                acc[2] += v[u] * f1.x; acc[3] += v[u] * f1.y;
            }
        }
        for (; j < cnt; j++) {
            int c = __shfl_sync(0xffffffffu, pk.x, j);
            float v = __int_as_float(__shfl_sync(0xffffffffu, pk.y, j));
            uint2 hw = ((const uint2*)(g_h0h + (size_t)c * HID))[lane];
            float2 f0 = __half22float2(*(__half2*)&hw.x);
            float2 f1 = __half22float2(*(__half2*)&hw.y);
            acc[0] += v * f0.x; acc[1] += v * f0.y;
            acc[2] += v * f1.x; acc[3] += v * f1.y;
        }
    }

    // ReLU + fp16 store; lane owns cols [4*lane, 4*lane+4)
    __half2 o0 = __floats2half2_rn(fmaxf(acc[0], 0.f), fmaxf(acc[1], 0.f));
    __half2 o1 = __floats2half2_rn(fmaxf(acc[2], 0.f), fmaxf(acc[3], 0.f));
    uint2 pkout = make_uint2(*(unsigned*)&o0, *(unsigned*)&o1);
    ((uint2*)(g_h1h + (size_t)r * HID))[lane] = pkout;
}

// ---------------------------------------------------------------------------
// GEMM2 (fp16 tensor cores): g_h2h = half(g_h1h @ W2 + b2).  M=100000,K=128,N=32.
// Block 256 thr (8 warps x 16 rows = 128 rows).  B-fragments prepacked in smem.
// ---------------------------------------------------------------------------
__global__ __launch_bounds__(256) void gemm2_mma_kernel(const float* __restrict__ W2,
                                                        const float* __restrict__ b2) {
    __shared__ uint2 Bfrag[8][4][32];   // [kstep][nfrag][lane] = {b0, b1}, 8 KB
    __shared__ float b2s[OUT_DIM];

    const int tid  = threadIdx.x;
    const int wid  = tid >> 5;
    const int lane = tid & 31;
    const int g    = lane >> 2;
    const int t    = lane & 3;

    if (tid < 32) {
#pragma unroll
        for (int ks = 0; ks < 8; ks++)
#pragma unroll
            for (int nf = 0; nf < 4; nf++) {
                int k0 = ks * 16 + 2 * t;
                int n  = nf * 8 + g;
                __half2 lo = __floats2half2_rn(W2[(size_t)k0 * OUT_DIM + n],
                                               W2[(size_t)(k0 + 1) * OUT_DIM + n]);
                __half2 hi = __floats2half2_rn(W2[(size_t)(k0 + 8) * OUT_DIM + n],
                                               W2[(size_t)(k0 + 9) * OUT_DIM + n]);
                Bfrag[ks][nf][lane] = make_uint2(*(unsigned*)&lo, *(unsigned*)&hi);
            }
    }
    if (tid < OUT_DIM) b2s[tid] = b2[tid];
    __syncthreads();

    const int r0 = blockIdx.x * 128 + wid * 16 + g;   // rows r0, r0+8
    const bool v0 = r0 < N_NODES;
    const bool v1 = (r0 + 8) < N_NODES;
    const unsigned* row0 = (const unsigned*)(g_h1h + (size_t)(v0 ? r0 : 0) * HID);
    const unsigned* row1 = (const unsigned*)(g_h1h + (size_t)(v1 ? r0 + 8 : 0) * HID);

    float acc[4][4];
#pragma unroll
    for (int nf = 0; nf < 4; nf++)
#pragma unroll
        for (int q = 0; q < 4; q++) acc[nf][q] = 0.f;

#pragma unroll
    for (int ks = 0; ks < 8; ks++) {
        const int h = ks * 8 + t;   // half2 index of element ks*16 + 2t
        unsigned a[4];
        a[0] = v0 ? row0[h] : 0u;
        a[1] = v1 ? row1[h] : 0u;
        a[2] = v0 ? row0[h + 4] : 0u;
        a[3] = v1 ? row1[h + 4] : 0u;
#pragma unroll
        for (int nf = 0; nf < 4; nf++) {
            uint2 b = Bfrag[ks][nf][lane];
            unsigned bb[2] = {b.x, b.y};
            mma_f16(acc[nf], a, bb);
        }
    }

#pragma unroll
    for (int nf = 0; nf < 4; nf++) {
        int n = nf * 8 + 2 * t;
        float bb0 = b2s[n], bb1 = b2s[n + 1];
        if (v0)
            *(__half2*)(g_h2h + (size_t)r0 * OUT_DIM + n) =
                __floats2half2_rn(acc[nf][0] + bb0, acc[nf][1] + bb1);
        if (v1)
            *(__half2*)(g_h2h + (size_t)(r0 + 8) * OUT_DIM + n) =
                __floats2half2_rn(acc[nf][2] + bb0, acc[nf][3] + bb1);
    }
}

// ---------------------------------------------------------------------------
// SpMM2: 16 lanes per row (half2 each); halves process alternating edges,
// 8 edges unrolled per half -> MLP 8.
// ---------------------------------------------------------------------------
__global__ __launch_bounds__(256) void spmm2_csr_kernel(float* __restrict__ out) {
    const int wid  = threadIdx.x >> 5;
    const int lane = threadIdx.x & 31;
    const int half = lane >> 4;
    const int l16  = lane & 15;
    const int r = blockIdx.x * 8 + wid;
    if (r >= N_NODES) return;

    const int s0 = g_rowptr[r];
    const int s1 = g_rowptr[r + 1];

    float2 acc = make_float2(0.f, 0.f);
    for (int base = s0; base < s1; base += 32) {
        int cnt = min(32, s1 - base);
        int2 pk = make_int2(0, 0);
        if (lane < cnt) pk = g_cedge[base + lane];

        int j = 0;
        for (; j + 16 <= cnt; j += 16) {
            int   c[8];
            float v[8];
#pragma unroll
            for (int u = 0; u < 8; u++) {
                int e = j + 2 * u + half;
                c[u] = __shfl_sync(0xffffffffu, pk.x, e);
                v[u] = __int_as_float(__shfl_sync(0xffffffffu, pk.y, e));
            }
            __half2 hv[8];
#pragma unroll
            for (int u = 0; u < 8; u++)
                hv[u] = ((const __half2*)(g_h2h + (size_t)c[u] * OUT_DIM))[l16];
#pragma unroll
            for (int u = 0; u < 8; u++) {
                float2 f = __half22float2(hv[u]);
                acc.x += v[u] * f.x;
                acc.y += v[u] * f.y;
            }
        }
        for (; j < cnt; j += 2) {
            int e = j + half;
            int esafe = (e < cnt) ? e : (cnt - 1);
            int c = __shfl_sync(0xffffffffu, pk.x, esafe);
            float v = __int_as_float(__shfl_sync(0xffffffffu, pk.y, esafe));
            if (e >= cnt) v = 0.f;
            __half2 hv = ((const __half2*)(g_h2h + (size_t)c * OUT_DIM))[l16];
            float2 f = __half22float2(hv);
            acc.x += v * f.x;
            acc.y += v * f.y;
        }
    }

    acc.x += __shfl_xor_sync(0xffffffffu, acc.x, 16);
    acc.y += __shfl_xor_sync(0xffffffffu, acc.y, 16);
    if (half == 0)
        *(float2*)(out + (size_t)r * OUT_DIM + 2 * l16) = acc;
}

// ---------------------------------------------------------------------------
// Launch.  CSR chain on side stream; gemm1 on main.  Submission order puts
// csr_scatter at ncu slot #4 (the remaining big unknown).
// ---------------------------------------------------------------------------
extern "C" void kernel_launch(void* const* d_in, const int* in_sizes, int n_in,
                              void* d_out, int out_size) {
    const float* x    = (const float*)d_in[0];
    const int*   erow = (const int*)d_in[1];
    const int*   ecol = (const int*)d_in[2];
    const float* eval = (const float*)d_in[3];
    const float* W1   = (const float*)d_in[4];
    const float* b1   = (const float*)d_in[5];
    const float* W2   = (const float*)d_in[6];
    const float* b2   = (const float*)d_in[7];
    float* out = (float*)d_out;
    const int E = in_sizes[1];

    static cudaStream_t s1 = nullptr;
    static cudaEvent_t ev_fork = nullptr, ev_join = nullptr;
    if (s1 == nullptr) {
        cudaStreamCreateWithFlags(&s1, cudaStreamNonBlocking);
        cudaEventCreateWithFlags(&ev_fork, cudaEventDisableTiming);
        cudaEventCreateWithFlags(&ev_join, cudaEventDisableTiming);
    }

    const int nb_nodes = (N_NODES + 255) / 256;
    const int nb_edges = (E + 255) / 256;
    const int nb_scan  = (N_NODES + 1023) / 1024;
    const int nb_rows8 = (N_NODES + 7) / 8;

    cudaEventRecord(ev_fork, 0);
    cudaStreamWaitEvent(s1, ev_fork, 0);

    // CSR chain on s1 (launches 1,2,3,4 — scatter is #4 for ncu)
    csr_count_kernel<<<nb_edges, 256, 0, s1>>>(erow, E);
    scan1_kernel<<<nb_scan, 1024, 0, s1>>>();
    scan23_kernel<<<nb_nodes, 256, 0, s1>>>(nb_scan, E);
    csr_scatter_kernel<<<nb_edges, 256, 0, s1>>>(erow, ecol, eval, E);
    cudaEventRecord(ev_join, s1);

    // GEMM1 on main stream
    gemm1_mma_kernel<<<(N_NODES + 127) / 128, 256>>>(x, W1, b1);

    // join, then SpMM1 -> GEMM2 -> SpMM2
    cudaStreamWaitEvent(0, ev_join, 0);
    spmm1_kernel<<<nb_rows8, 256>>>();
    gemm2_mma_kernel<<<(N_NODES + 127) / 128, 256>>>(W2, b2);
    spmm2_csr_kernel<<<nb_rows8, 256>>>(out);
}